// round 3
// baseline (speedup 1.0000x reference)
#include <cuda_runtime.h>
#include <math.h>

#define BATCH 2
#define SEQ   2048
#define DMODEL 2048
#define QHEADS 32
#define KVHEADS 8
#define HDIM  64
#define MROWS (BATCH * SEQ)   // 4096

// Scratch (device globals; no runtime allocation allowed)
__device__ float g_q [MROWS * (QHEADS  * HDIM)]; // 4096 x 2048
__device__ float g_k [MROWS * (KVHEADS * HDIM)]; // 4096 x 512
__device__ float g_v [MROWS * (KVHEADS * HDIM)]; // 4096 x 512
__device__ float g_ao[MROWS * DMODEL];           // 4096 x 2048

// ---------------------------------------------------------------------------
// C[M,N] = A[M,K] @ W[N,K]^T   (fp32, 64x64x16 tiles, 4x4 per thread)
// ---------------------------------------------------------------------------
__global__ __launch_bounds__(256)
void gemm_nt_kernel(const float* __restrict__ A, const float* __restrict__ W,
                    float* __restrict__ C, int M, int N, int K)
{
    __shared__ float As[16][64];
    __shared__ float Ws[16][64];

    const int tid = threadIdx.x;
    const int tx  = tid & 15;   // N direction (x4)
    const int ty  = tid >> 4;   // M direction (x4)

    const int row0 = blockIdx.y * 64;
    const int col0 = blockIdx.x * 64;

    // load mapping: each thread loads one float4 of A and one of W per k-step
    const int l_row  = tid >> 2;        // 0..63
    const int l_col4 = (tid & 3) * 4;   // 0,4,8,12

    float acc[4][4];
#pragma unroll
    for (int i = 0; i < 4; i++)
#pragma unroll
        for (int j = 0; j < 4; j++) acc[i][j] = 0.f;

    const float* Ap = A + (size_t)(row0 + l_row) * K + l_col4;
    const float* Wp = W + (size_t)(col0 + l_row) * K + l_col4;

    for (int k0 = 0; k0 < K; k0 += 16) {
        float4 av = *(const float4*)(Ap + k0);
        float4 wv = *(const float4*)(Wp + k0);
        As[l_col4 + 0][l_row] = av.x;
        As[l_col4 + 1][l_row] = av.y;
        As[l_col4 + 2][l_row] = av.z;
        As[l_col4 + 3][l_row] = av.w;
        Ws[l_col4 + 0][l_row] = wv.x;
        Ws[l_col4 + 1][l_row] = wv.y;
        Ws[l_col4 + 2][l_row] = wv.z;
        Ws[l_col4 + 3][l_row] = wv.w;
        __syncthreads();

#pragma unroll
        for (int kk = 0; kk < 16; kk++) {
            float4 a4 = *(const float4*)&As[kk][ty * 4];
            float4 w4 = *(const float4*)&Ws[kk][tx * 4];
            float a[4] = {a4.x, a4.y, a4.z, a4.w};
            float w[4] = {w4.x, w4.y, w4.z, w4.w};
#pragma unroll
            for (int i = 0; i < 4; i++)
#pragma unroll
                for (int j = 0; j < 4; j++)
                    acc[i][j] = fmaf(a[i], w[j], acc[i][j]);
        }
        __syncthreads();
    }

#pragma unroll
    for (int i = 0; i < 4; i++) {
        float4 o = make_float4(acc[i][0], acc[i][1], acc[i][2], acc[i][3]);
        *(float4*)&C[(size_t)(row0 + ty * 4 + i) * N + col0 + tx * 4] = o;
    }
}

// ---------------------------------------------------------------------------
// RoPE in-place on [MROWS, nheads*64]; pair layout interleaved (even/odd)
// ---------------------------------------------------------------------------
__global__ void rope_kernel(float* __restrict__ buf, int nheads, int total)
{
    int idx = blockIdx.x * blockDim.x + threadIdx.x;
    if (idx >= total) return;
    int pair = idx & 31;            // 0..31
    int t    = idx >> 5;
    int h    = t % nheads;
    int row  = t / nheads;
    int pos  = row & (SEQ - 1);     // row % SEQ

    double inv = pow(10000.0, -(2.0 * pair) / 64.0);
    double ang = (double)pos * inv;
    double c, s;
    sincos(ang, &s, &c);

    float* p = buf + (size_t)row * (nheads * HDIM) + h * HDIM + pair * 2;
    float x1 = p[0], x2 = p[1];
    p[0] = (float)((double)x1 * c - (double)x2 * s);
    p[1] = (float)((double)x2 * c + (double)x1 * s);
}

// ---------------------------------------------------------------------------
// Causal flash attention. grid=(SEQ/128, QHEADS, BATCH), block=128.
// One query row per thread; K/V tiles (64x64) staged in smem.
// ---------------------------------------------------------------------------
__global__ __launch_bounds__(128)
void attn_kernel(const float* __restrict__ Q, const float* __restrict__ Kb,
                 const float* __restrict__ Vb, float* __restrict__ O)
{
    __shared__ float Ks[64][64];
    __shared__ float Vs[64][64];

    const int qt  = blockIdx.x;
    const int h   = blockIdx.y;
    const int b   = blockIdx.z;
    const int kvh = h >> 2;             // rep = 4
    const int tid = threadIdx.x;
    const int qrow = qt * 128 + tid;    // global seq index of this query

    // q row -> registers
    float q[HDIM];
    const float* qp = Q + (size_t)(b * SEQ + qrow) * (QHEADS * HDIM) + h * HDIM;
#pragma unroll
    for (int d4 = 0; d4 < 16; d4++) {
        float4 v = *(const float4*)(qp + d4 * 4);
        q[4 * d4 + 0] = v.x; q[4 * d4 + 1] = v.y;
        q[4 * d4 + 2] = v.z; q[4 * d4 + 3] = v.w;
    }

    float m = -INFINITY, l = 0.f;
    float o[HDIM];
#pragma unroll
    for (int d = 0; d < HDIM; d++) o[d] = 0.f;

    const int kend = qt * 128 + 127;    // block-max query -> last needed key
    const size_t kvStride = KVHEADS * HDIM;

    for (int k0 = 0; k0 <= kend; k0 += 64) {
        // stage K,V tiles: 1024 float4 each, 128 threads -> 8 float4/thread
#pragma unroll
        for (int t = 0; t < 8; t++) {
            int idx  = tid + t * 128;
            int r    = idx >> 4;          // 0..63
            int c4   = (idx & 15) * 4;    // 0..60
            const float* kp = Kb + (size_t)(b * SEQ + k0 + r) * kvStride + kvh * HDIM + c4;
            const float* vp = Vb + (size_t)(b * SEQ + k0 + r) * kvStride + kvh * HDIM + c4;
            *(float4*)&Ks[r][c4] = *(const float4*)kp;
            *(float4*)&Vs[r][c4] = *(const float4*)vp;
        }
        __syncthreads();

        int jmax = qrow - k0;             // keys with index <= qrow
        if (jmax > 63) jmax = 63;
        for (int j = 0; j <= jmax; j++) {
            float s = 0.f;
            const float4* k4 = (const float4*)Ks[j];
#pragma unroll
            for (int d4 = 0; d4 < 16; d4++) {
                float4 kv = k4[d4];
                s = fmaf(q[4 * d4 + 0], kv.x, s);
                s = fmaf(q[4 * d4 + 1], kv.y, s);
                s = fmaf(q[4 * d4 + 2], kv.z, s);
                s = fmaf(q[4 * d4 + 3], kv.w, s);
            }
            s *= 0.125f;  // 1/sqrt(64)
            float mnew  = fmaxf(m, s);
            float scale = __expf(m - mnew) ;   // fast exp ok: |m-mnew| small
            float p     = __expf(s - mnew);
            l = l * scale + p;
            const float4* v4 = (const float4*)Vs[j];
#pragma unroll
            for (int d4 = 0; d4 < 16; d4++) {
                float4 vv = v4[d4];
                o[4 * d4 + 0] = fmaf(p, vv.x, o[4 * d4 + 0] * scale);
                o[4 * d4 + 1] = fmaf(p, vv.y, o[4 * d4 + 1] * scale);
                o[4 * d4 + 2] = fmaf(p, vv.z, o[4 * d4 + 2] * scale);
                o[4 * d4 + 3] = fmaf(p, vv.w, o[4 * d4 + 3] * scale);
            }
            m = mnew;
        }
        __syncthreads();
    }

    float inv = 1.f / l;
    float* op = O + (size_t)(b * SEQ + qrow) * DMODEL + h * HDIM;
#pragma unroll
    for (int d4 = 0; d4 < 16; d4++) {
        float4 v = make_float4(o[4 * d4 + 0] * inv, o[4 * d4 + 1] * inv,
                               o[4 * d4 + 2] * inv, o[4 * d4 + 3] * inv);
        *(float4*)(op + d4 * 4) = v;
    }
}

// ---------------------------------------------------------------------------
extern "C" void kernel_launch(void* const* d_in, const int* in_sizes, int n_in,
                              void* d_out, int out_size)
{
    const float* x  = (const float*)d_in[0];
    // d_in[1] = attention_mask: all-true by construction; not read.
    const float* wq = (const float*)d_in[2];
    const float* wk = (const float*)d_in[3];
    const float* wv = (const float*)d_in[4];
    const float* wo = (const float*)d_in[5];
    float* out = (float*)d_out;

    void *pq, *pk, *pv, *pao;
    cudaGetSymbolAddress(&pq,  g_q);
    cudaGetSymbolAddress(&pk,  g_k);
    cudaGetSymbolAddress(&pv,  g_v);
    cudaGetSymbolAddress(&pao, g_ao);
    float* qb  = (float*)pq;
    float* kb  = (float*)pk;
    float* vb  = (float*)pv;
    float* aob = (float*)pao;

    // QKV projections
    {
        dim3 blk(256);
        dim3 gq(QHEADS  * HDIM / 64, MROWS / 64);
        dim3 gk(KVHEADS * HDIM / 64, MROWS / 64);
        gemm_nt_kernel<<<gq, blk>>>(x, wq, qb, MROWS, QHEADS  * HDIM, DMODEL);
        gemm_nt_kernel<<<gk, blk>>>(x, wk, kb, MROWS, KVHEADS * HDIM, DMODEL);
        gemm_nt_kernel<<<gk, blk>>>(x, wv, vb, MROWS, KVHEADS * HDIM, DMODEL);
    }

    // RoPE on q and k
    {
        int totq = MROWS * QHEADS  * 32;
        int totk = MROWS * KVHEADS * 32;
        rope_kernel<<<(totq + 255) / 256, 256>>>(qb, QHEADS,  totq);
        rope_kernel<<<(totk + 255) / 256, 256>>>(kb, KVHEADS, totk);
    }

    // Attention
    {
        dim3 grid(SEQ / 128, QHEADS, BATCH);
        attn_kernel<<<grid, 128>>>(qb, kb, vb, aob);
    }

    // Output projection
    {
        dim3 blk(256);
        dim3 go(DMODEL / 64, MROWS / 64);
        gemm_nt_kernel<<<go, blk>>>(aob, wo, out, MROWS, DMODEL, DMODEL);
    }
}

// round 5
// speedup vs baseline: 2.2121x; 2.2121x over previous
#include <cuda_runtime.h>
#include <math.h>
#include <stdint.h>

#define BATCH   2
#define SEQ     2048
#define DMODEL  2048
#define QHEADS  32
#define KVHEADS 8
#define HDIM    64
#define MROWS   (BATCH * SEQ)   // 4096

// ---------------- scratch (device globals; no runtime allocation) ----------
__device__ float  g_q  [MROWS * (QHEADS  * HDIM)];
__device__ float  g_k  [MROWS * (KVHEADS * HDIM)];
__device__ float  g_v  [MROWS * (KVHEADS * HDIM)];
__device__ float  g_ao [MROWS * DMODEL];
__device__ float2 g_rope[SEQ * 32];           // (cos, sin) per (pos, pair)

// ---------------------------------------------------------------------------
// RoPE table: double precision once, tiny kernel.
// ---------------------------------------------------------------------------
__global__ void rope_table_kernel(float2* __restrict__ tbl)
{
    int i = blockIdx.x * blockDim.x + threadIdx.x;
    if (i >= SEQ * 32) return;
    int pair = i & 31;
    int pos  = i >> 5;
    double inv = pow(10000.0, -(2.0 * pair) / 64.0);
    double a   = (double)pos * inv;
    tbl[i] = make_float2((float)cos(a), (float)sin(a));
}

// ---------------------------------------------------------------------------
// TF32 tensor-core GEMM:  C[M,N] = A[M,K] @ W[N,K]^T   (+ optional fused RoPE)
// BM=128 BN=128 BK=16, 256 threads (8 warps as 2m x 4n), warp tile 64x32.
// smem tiles pre-swizzled into mma-fragment layout:
//   A word addr = kt*1168 + mt*144 + rg*36 + ln   (ln = 4*(row&7) + (k&3))
//   B word addr = kt*1296 + nt*80  + rg*40 + ln   (ln = 4*(n&7)   + (k&3))
// ---------------------------------------------------------------------------
#define AKT  1168
#define AMT  144
#define ARG  36
#define ABUF 2336
#define BKT  1296
#define BNT  80
#define BRG  40
#define BBUF 2592

__device__ __forceinline__ uint32_t f2tf(float f)
{
    uint32_t u;
    asm("cvt.rna.tf32.f32 %0, %1;" : "=r"(u) : "f"(f));
    return u;
}

__device__ __forceinline__ void mma8(float* c, const uint32_t* a, const uint32_t* b)
{
    asm volatile(
        "mma.sync.aligned.m16n8k8.row.col.f32.tf32.tf32.f32 "
        "{%0,%1,%2,%3}, {%4,%5,%6,%7}, {%8,%9}, {%0,%1,%2,%3};"
        : "+f"(c[0]), "+f"(c[1]), "+f"(c[2]), "+f"(c[3])
        : "r"(a[0]), "r"(a[1]), "r"(a[2]), "r"(a[3]), "r"(b[0]), "r"(b[1]));
}

__device__ __forceinline__ void gemm_tile(
    const float* __restrict__ A, const float* __restrict__ W, float* __restrict__ C,
    int N, int K, int row0, int col0, int rope, const float2* __restrict__ tbl,
    uint32_t* sA, uint32_t* sB)
{
    const int tid  = threadIdx.x;
    const int lane = tid & 31;
    const int wid  = tid >> 5;
    const int wm   = wid & 1;     // 0..1  (m)
    const int wn   = wid >> 1;    // 0..3  (n)

    // invariant load/store positions (each thread: 2 float4 of A, 2 of W)
    int a_st[2], b_st[2], a_m[2], ab_k4[2], b_n[2];
#pragma unroll
    for (int t = 0; t < 2; t++) {
        int idx = tid + t * 256;
        int m   = idx >> 2;
        int k4  = (idx & 3) * 4;
        a_m[t] = m; b_n[t] = m; ab_k4[t] = k4;
        int kt   = k4 >> 3;
        int kin0 = k4 & 7;
        int arg  = ((kin0 >= 4) ? 2 : 0) | (((m & 15) >= 8) ? 1 : 0);
        a_st[t]  = kt * AKT + (m >> 4) * AMT + arg * ARG + (m & 7) * 4;
        int brg  = (kin0 >= 4) ? 1 : 0;
        b_st[t]  = kt * BKT + (m >> 3) * BNT + brg * BRG + (m & 7) * 4;
    }

    float acc[4][4][4];
#pragma unroll
    for (int i = 0; i < 4; i++)
#pragma unroll
        for (int j = 0; j < 4; j++)
#pragma unroll
            for (int r = 0; r < 4; r++) acc[i][j][r] = 0.f;

    float4 ar[2], br[2];
#pragma unroll
    for (int t = 0; t < 2; t++) {
        ar[t] = *(const float4*)(A + (size_t)(row0 + a_m[t]) * K + ab_k4[t]);
        br[t] = *(const float4*)(W + (size_t)(col0 + b_n[t]) * K + ab_k4[t]);
    }
#pragma unroll
    for (int t = 0; t < 2; t++) {
        uint4 av = make_uint4(f2tf(ar[t].x), f2tf(ar[t].y), f2tf(ar[t].z), f2tf(ar[t].w));
        uint4 bv = make_uint4(f2tf(br[t].x), f2tf(br[t].y), f2tf(br[t].z), f2tf(br[t].w));
        *(uint4*)(sA + a_st[t]) = av;
        *(uint4*)(sB + b_st[t]) = bv;
    }
    __syncthreads();

    int buf = 0;
    for (int k0 = 16; ; k0 += 16) {
        const bool more = (k0 < K);
        if (more) {
#pragma unroll
            for (int t = 0; t < 2; t++) {
                ar[t] = *(const float4*)(A + (size_t)(row0 + a_m[t]) * K + k0 + ab_k4[t]);
                br[t] = *(const float4*)(W + (size_t)(col0 + b_n[t]) * K + k0 + ab_k4[t]);
            }
        }
        const uint32_t* Ab = sA + buf * ABUF;
        const uint32_t* Bb = sB + buf * BBUF;
#pragma unroll
        for (int kt = 0; kt < 2; kt++) {
            uint32_t af[4][4], bf[4][2];
#pragma unroll
            for (int mt = 0; mt < 4; mt++) {
                int base = kt * AKT + (wm * 4 + mt) * AMT + lane;
#pragma unroll
                for (int rg = 0; rg < 4; rg++) af[mt][rg] = Ab[base + rg * ARG];
            }
#pragma unroll
            for (int nt = 0; nt < 4; nt++) {
                int base = kt * BKT + (wn * 4 + nt) * BNT + lane;
#pragma unroll
                for (int rg = 0; rg < 2; rg++) bf[nt][rg] = Bb[base + rg * BRG];
            }
#pragma unroll
            for (int mt = 0; mt < 4; mt++)
#pragma unroll
                for (int nt = 0; nt < 4; nt++)
                    mma8(acc[mt][nt], af[mt], bf[nt]);
        }
        if (!more) break;
        uint32_t* An = sA + (buf ^ 1) * ABUF;
        uint32_t* Bn = sB + (buf ^ 1) * BBUF;
#pragma unroll
        for (int t = 0; t < 2; t++) {
            uint4 av = make_uint4(f2tf(ar[t].x), f2tf(ar[t].y), f2tf(ar[t].z), f2tf(ar[t].w));
            uint4 bv = make_uint4(f2tf(br[t].x), f2tf(br[t].y), f2tf(br[t].z), f2tf(br[t].w));
            *(uint4*)(An + a_st[t]) = av;
            *(uint4*)(Bn + b_st[t]) = bv;
        }
        __syncthreads();
        buf ^= 1;
    }

    // epilogue (+ fused RoPE: (c0,c1)/(c2,c3) are interleaved rope pairs)
    const int r_base = row0 + wm * 64 + (lane >> 2);
    const int c_base = col0 + wn * 32 + (lane & 3) * 2;
#pragma unroll
    for (int mt = 0; mt < 4; mt++) {
#pragma unroll
        for (int nt = 0; nt < 4; nt++) {
            int r  = r_base + mt * 16;
            int cc = c_base + nt * 8;
            float v0 = acc[mt][nt][0], v1 = acc[mt][nt][1];
            float v2 = acc[mt][nt][2], v3 = acc[mt][nt][3];
            if (rope) {
                int pair = (cc & 63) >> 1;
                float2 cs1 = tbl[(r       & (SEQ - 1)) * 32 + pair];
                float2 cs2 = tbl[((r + 8) & (SEQ - 1)) * 32 + pair];
                float o0 = v0 * cs1.x - v1 * cs1.y;
                float o1 = v1 * cs1.x + v0 * cs1.y;
                float o2 = v2 * cs2.x - v3 * cs2.y;
                float o3 = v3 * cs2.x + v2 * cs2.y;
                v0 = o0; v1 = o1; v2 = o2; v3 = o3;
            }
            *(float2*)&C[(size_t)r * N + cc]       = make_float2(v0, v1);
            *(float2*)&C[(size_t)(r + 8) * N + cc] = make_float2(v2, v3);
        }
    }
}

__global__ __launch_bounds__(256)
void gemm_kernel(const float* __restrict__ A, const float* __restrict__ W,
                 float* __restrict__ C, int N, int K, int rope,
                 const float2* __restrict__ tbl)
{
    __shared__ uint32_t sA[2 * ABUF];
    __shared__ uint32_t sB[2 * BBUF];
    gemm_tile(A, W, C, N, K, blockIdx.y * 128, blockIdx.x * 128, rope, tbl, sA, sB);
}

__global__ __launch_bounds__(256)
void gemm_kv_kernel(const float* __restrict__ A,
                    const float* __restrict__ Wk, const float* __restrict__ Wv,
                    float* __restrict__ Ck, float* __restrict__ Cv,
                    int K, const float2* __restrict__ tbl)
{
    __shared__ uint32_t sA[2 * ABUF];
    __shared__ uint32_t sB[2 * BBUF];
    int bx = blockIdx.x;
    if (bx < 4)
        gemm_tile(A, Wk, Ck, 512, K, blockIdx.y * 128, bx * 128, 1, tbl, sA, sB);
    else
        gemm_tile(A, Wv, Cv, 512, K, blockIdx.y * 128, (bx - 4) * 128, 0, tbl, sA, sB);
}

// ---------------------------------------------------------------------------
// Causal flash attention, packed f32x2 math, 16-key chunks.
// grid=(SEQ/128, QHEADS, BATCH), block=128, 1 query row per thread.
// ---------------------------------------------------------------------------
typedef unsigned long long u64;

__device__ __forceinline__ u64 pk2(float lo, float hi)
{
    u64 r; asm("mov.b64 %0, {%1,%2};" : "=l"(r) : "f"(lo), "f"(hi)); return r;
}
__device__ __forceinline__ void upk2(u64 v, float& lo, float& hi)
{
    asm("mov.b64 {%0,%1}, %2;" : "=f"(lo), "=f"(hi) : "l"(v));
}
__device__ __forceinline__ u64 fma2(u64 a, u64 b, u64 c)
{
    u64 d; asm("fma.rn.f32x2 %0, %1, %2, %3;" : "=l"(d) : "l"(a), "l"(b), "l"(c)); return d;
}
__device__ __forceinline__ u64 mul2(u64 a, u64 b)
{
    u64 d; asm("mul.rn.f32x2 %0, %1, %2;" : "=l"(d) : "l"(a), "l"(b)); return d;
}

__global__ __launch_bounds__(128)
void attn_kernel(const float* __restrict__ Q, const float* __restrict__ Kb,
                 const float* __restrict__ Vb, float* __restrict__ O)
{
    __shared__ float Ks[64][64];
    __shared__ float Vs[64][64];

    const int qt   = blockIdx.x;
    const int h    = blockIdx.y;
    const int b    = blockIdx.z;
    const int kvh  = h >> 2;
    const int tid  = threadIdx.x;
    const int qrow = qt * 128 + tid;

    // q (pre-scaled by 1/sqrt(64)) as packed pairs
    u64 q2[32];
    {
        const float* qp = Q + (size_t)(b * SEQ + qrow) * (QHEADS * HDIM) + h * HDIM;
#pragma unroll
        for (int d4 = 0; d4 < 16; d4++) {
            float4 v = *(const float4*)(qp + d4 * 4);
            q2[2 * d4]     = pk2(v.x * 0.125f, v.y * 0.125f);
            q2[2 * d4 + 1] = pk2(v.z * 0.125f, v.w * 0.125f);
        }
    }

    float m = -INFINITY, l = 0.f;
    u64 o2[32];
#pragma unroll
    for (int i = 0; i < 32; i++) o2[i] = 0ull;

    const int    kend     = qt * 128 + 127;
    const size_t kvStride = KVHEADS * HDIM;

    for (int k0 = 0; k0 <= kend; k0 += 64) {
#pragma unroll
        for (int t = 0; t < 8; t++) {
            int idx = tid + t * 128;
            int r   = idx >> 4;
            int c4  = (idx & 15) * 4;
            const float* kp = Kb + (size_t)(b * SEQ + k0 + r) * kvStride + kvh * HDIM + c4;
            const float* vp = Vb + (size_t)(b * SEQ + k0 + r) * kvStride + kvh * HDIM + c4;
            *(float4*)&Ks[r][c4] = *(const float4*)kp;
            *(float4*)&Vs[r][c4] = *(const float4*)vp;
        }
        __syncthreads();

        int jmax = qrow - k0;
        if (jmax > 63) jmax = 63;
        for (int c0 = 0; c0 <= jmax; c0 += 16) {
            float sc[16];
#pragma unroll
            for (int jj = 0; jj < 16; jj++) {
                const ulonglong2* kp = (const ulonglong2*)Ks[c0 + jj];
                u64 a2 = 0ull;
#pragma unroll
                for (int d = 0; d < 16; d++) {
                    ulonglong2 kk = kp[d];
                    a2 = fma2(q2[2 * d],     kk.x, a2);
                    a2 = fma2(q2[2 * d + 1], kk.y, a2);
                }
                float lo, hi; upk2(a2, lo, hi);
                float s = lo + hi;
                sc[jj] = (c0 + jj <= jmax) ? s : -INFINITY;
            }
            float cmax = sc[0];
#pragma unroll
            for (int jj = 1; jj < 16; jj++) cmax = fmaxf(cmax, sc[jj]);
            float mnew  = fmaxf(m, cmax);
            float scale = __expf(m - mnew);
            l *= scale;
            u64 s2 = pk2(scale, scale);
#pragma unroll
            for (int i = 0; i < 32; i++) o2[i] = mul2(o2[i], s2);
#pragma unroll
            for (int jj = 0; jj < 16; jj++) {
                float p = __expf(sc[jj] - mnew);
                l += p;
                u64 p2 = pk2(p, p);
                const ulonglong2* vp = (const ulonglong2*)Vs[c0 + jj];
#pragma unroll
                for (int d = 0; d < 16; d++) {
                    ulonglong2 vv = vp[d];
                    o2[2 * d]     = fma2(p2, vv.x, o2[2 * d]);
                    o2[2 * d + 1] = fma2(p2, vv.y, o2[2 * d + 1]);
                }
            }
            m = mnew;
        }
        __syncthreads();
    }

    float inv = 1.f / l;
    float* op = O + (size_t)(b * SEQ + qrow) * DMODEL + h * HDIM;
#pragma unroll
    for (int d = 0; d < 16; d++) {
        float a0, a1, a2, a3;
        upk2(o2[2 * d],     a0, a1);
        upk2(o2[2 * d + 1], a2, a3);
        *(float4*)(op + d * 4) = make_float4(a0 * inv, a1 * inv, a2 * inv, a3 * inv);
    }
}

// ---------------------------------------------------------------------------
extern "C" void kernel_launch(void* const* d_in, const int* in_sizes, int n_in,
                              void* d_out, int out_size)
{
    const float* x  = (const float*)d_in[0];
    // d_in[1] = attention_mask: all-true by construction; not read.
    const float* wq = (const float*)d_in[2];
    const float* wk = (const float*)d_in[3];
    const float* wv = (const float*)d_in[4];
    const float* wo = (const float*)d_in[5];
    float* out = (float*)d_out;

    void *pq, *pk, *pv, *pao, *prt;
    cudaGetSymbolAddress(&pq,  g_q);
    cudaGetSymbolAddress(&pk,  g_k);
    cudaGetSymbolAddress(&pv,  g_v);
    cudaGetSymbolAddress(&pao, g_ao);
    cudaGetSymbolAddress(&prt, g_rope);
    float*  qb  = (float*)pq;
    float*  kb  = (float*)pk;
    float*  vb  = (float*)pv;
    float*  aob = (float*)pao;
    float2* tbl = (float2*)prt;

    // RoPE cos/sin table
    rope_table_kernel<<<(SEQ * 32 + 255) / 256, 256>>>(tbl);

    // Projections (RoPE fused into Q and K epilogues)
    {
        dim3 blk(256);
        gemm_kernel<<<dim3(16, 32), blk>>>(x, wq, qb, 2048, 2048, 1, tbl);
        gemm_kv_kernel<<<dim3(8, 32), blk>>>(x, wk, wv, kb, vb, 2048, tbl);
    }

    // Attention
    {
        dim3 grid(SEQ / 128, QHEADS, BATCH);
        attn_kernel<<<grid, 128>>>(qb, kb, vb, aob);
    }

    // Output projection
    gemm_kernel<<<dim3(16, 32), 256>>>(aob, wo, out, 2048, 2048, 0, tbl);
}

// round 6
// speedup vs baseline: 3.9259x; 1.7747x over previous
#include <cuda_runtime.h>
#include <math.h>
#include <stdint.h>

#define BATCH   2
#define SEQ     2048
#define DMODEL  2048
#define QHEADS  32
#define KVHEADS 8
#define HDIM    64
#define MROWS   (BATCH * SEQ)   // 4096

// ---------------- scratch (device globals; no runtime allocation) ----------
__device__ float  g_q  [MROWS * (QHEADS  * HDIM)];
__device__ float  g_k  [MROWS * (KVHEADS * HDIM)];
__device__ float  g_v  [MROWS * (KVHEADS * HDIM)];
__device__ float  g_ao [MROWS * DMODEL];
__device__ float2 g_rope[SEQ * 32];           // (cos, sin) per (pos, pair)

// ---------------------------------------------------------------------------
// RoPE table: double precision once, tiny kernel.
// ---------------------------------------------------------------------------
__global__ void rope_table_kernel(float2* __restrict__ tbl)
{
    int i = blockIdx.x * blockDim.x + threadIdx.x;
    if (i >= SEQ * 32) return;
    int pair = i & 31;
    int pos  = i >> 5;
    double inv = pow(10000.0, -(2.0 * pair) / 64.0);
    double a   = (double)pos * inv;
    tbl[i] = make_float2((float)cos(a), (float)sin(a));
}

// ---------------------------------------------------------------------------
// common tf32 helpers
// ---------------------------------------------------------------------------
__device__ __forceinline__ uint32_t f2tf(float f)
{
    uint32_t u;
    asm("cvt.rna.tf32.f32 %0, %1;" : "=r"(u) : "f"(f));
    return u;
}

__device__ __forceinline__ void mma8(float* c, const uint32_t* a, const uint32_t* b)
{
    asm volatile(
        "mma.sync.aligned.m16n8k8.row.col.f32.tf32.tf32.f32 "
        "{%0,%1,%2,%3}, {%4,%5,%6,%7}, {%8,%9}, {%0,%1,%2,%3};"
        : "+f"(c[0]), "+f"(c[1]), "+f"(c[2]), "+f"(c[3])
        : "r"(a[0]), "r"(a[1]), "r"(a[2]), "r"(a[3]), "r"(b[0]), "r"(b[1]));
}

// ---------------------------------------------------------------------------
// TF32 tensor-core GEMM:  C[M,N] = A[M,K] @ W[N,K]^T   (+ optional fused RoPE)
// BM=128 BN=128 BK=16, 256 threads (8 warps as 2m x 4n), warp tile 64x32.
// ---------------------------------------------------------------------------
#define AKT  1168
#define AMT  144
#define ARG  36
#define ABUF 2336
#define BKT  1296
#define BNT  80
#define BRG  40
#define BBUF 2592

__device__ __forceinline__ void gemm_tile(
    const float* __restrict__ A, const float* __restrict__ W, float* __restrict__ C,
    int N, int K, int row0, int col0, int rope, const float2* __restrict__ tbl,
    uint32_t* sA, uint32_t* sB)
{
    const int tid  = threadIdx.x;
    const int lane = tid & 31;
    const int wid  = tid >> 5;
    const int wm   = wid & 1;
    const int wn   = wid >> 1;

    int a_st[2], b_st[2], a_m[2], ab_k4[2], b_n[2];
#pragma unroll
    for (int t = 0; t < 2; t++) {
        int idx = tid + t * 256;
        int m   = idx >> 2;
        int k4  = (idx & 3) * 4;
        a_m[t] = m; b_n[t] = m; ab_k4[t] = k4;
        int kt   = k4 >> 3;
        int kin0 = k4 & 7;
        int arg  = ((kin0 >= 4) ? 2 : 0) | (((m & 15) >= 8) ? 1 : 0);
        a_st[t]  = kt * AKT + (m >> 4) * AMT + arg * ARG + (m & 7) * 4;
        int brg  = (kin0 >= 4) ? 1 : 0;
        b_st[t]  = kt * BKT + (m >> 3) * BNT + brg * BRG + (m & 7) * 4;
    }

    float acc[4][4][4];
#pragma unroll
    for (int i = 0; i < 4; i++)
#pragma unroll
        for (int j = 0; j < 4; j++)
#pragma unroll
            for (int r = 0; r < 4; r++) acc[i][j][r] = 0.f;

    float4 ar[2], br[2];
#pragma unroll
    for (int t = 0; t < 2; t++) {
        ar[t] = *(const float4*)(A + (size_t)(row0 + a_m[t]) * K + ab_k4[t]);
        br[t] = *(const float4*)(W + (size_t)(col0 + b_n[t]) * K + ab_k4[t]);
    }
#pragma unroll
    for (int t = 0; t < 2; t++) {
        uint4 av = make_uint4(f2tf(ar[t].x), f2tf(ar[t].y), f2tf(ar[t].z), f2tf(ar[t].w));
        uint4 bv = make_uint4(f2tf(br[t].x), f2tf(br[t].y), f2tf(br[t].z), f2tf(br[t].w));
        *(uint4*)(sA + a_st[t]) = av;
        *(uint4*)(sB + b_st[t]) = bv;
    }
    __syncthreads();

    int buf = 0;
    for (int k0 = 16; ; k0 += 16) {
        const bool more = (k0 < K);
        if (more) {
#pragma unroll
            for (int t = 0; t < 2; t++) {
                ar[t] = *(const float4*)(A + (size_t)(row0 + a_m[t]) * K + k0 + ab_k4[t]);
                br[t] = *(const float4*)(W + (size_t)(col0 + b_n[t]) * K + k0 + ab_k4[t]);
            }
        }
        const uint32_t* Ab = sA + buf * ABUF;
        const uint32_t* Bb = sB + buf * BBUF;
#pragma unroll
        for (int kt = 0; kt < 2; kt++) {
            uint32_t af[4][4], bf[4][2];
#pragma unroll
            for (int mt = 0; mt < 4; mt++) {
                int base = kt * AKT + (wm * 4 + mt) * AMT + lane;
#pragma unroll
                for (int rg = 0; rg < 4; rg++) af[mt][rg] = Ab[base + rg * ARG];
            }
#pragma unroll
            for (int nt = 0; nt < 4; nt++) {
                int base = kt * BKT + (wn * 4 + nt) * BNT + lane;
#pragma unroll
                for (int rg = 0; rg < 2; rg++) bf[nt][rg] = Bb[base + rg * BRG];
            }
#pragma unroll
            for (int mt = 0; mt < 4; mt++)
#pragma unroll
                for (int nt = 0; nt < 4; nt++)
                    mma8(acc[mt][nt], af[mt], bf[nt]);
        }
        if (!more) break;
        uint32_t* An = sA + (buf ^ 1) * ABUF;
        uint32_t* Bn = sB + (buf ^ 1) * BBUF;
#pragma unroll
        for (int t = 0; t < 2; t++) {
            uint4 av = make_uint4(f2tf(ar[t].x), f2tf(ar[t].y), f2tf(ar[t].z), f2tf(ar[t].w));
            uint4 bv = make_uint4(f2tf(br[t].x), f2tf(br[t].y), f2tf(br[t].z), f2tf(br[t].w));
            *(uint4*)(An + a_st[t]) = av;
            *(uint4*)(Bn + b_st[t]) = bv;
        }
        __syncthreads();
        buf ^= 1;
    }

    const int r_base = row0 + wm * 64 + (lane >> 2);
    const int c_base = col0 + wn * 32 + (lane & 3) * 2;
#pragma unroll
    for (int mt = 0; mt < 4; mt++) {
#pragma unroll
        for (int nt = 0; nt < 4; nt++) {
            int r  = r_base + mt * 16;
            int cc = c_base + nt * 8;
            float v0 = acc[mt][nt][0], v1 = acc[mt][nt][1];
            float v2 = acc[mt][nt][2], v3 = acc[mt][nt][3];
            if (rope) {
                int pair = (cc & 63) >> 1;
                float2 cs1 = tbl[(r       & (SEQ - 1)) * 32 + pair];
                float2 cs2 = tbl[((r + 8) & (SEQ - 1)) * 32 + pair];
                float o0 = v0 * cs1.x - v1 * cs1.y;
                float o1 = v1 * cs1.x + v0 * cs1.y;
                float o2 = v2 * cs2.x - v3 * cs2.y;
                float o3 = v3 * cs2.x + v2 * cs2.y;
                v0 = o0; v1 = o1; v2 = o2; v3 = o3;
            }
            *(float2*)&C[(size_t)r * N + cc]       = make_float2(v0, v1);
            *(float2*)&C[(size_t)(r + 8) * N + cc] = make_float2(v2, v3);
        }
    }
}

__global__ __launch_bounds__(256)
void gemm_kernel(const float* __restrict__ A, const float* __restrict__ W,
                 float* __restrict__ C, int N, int K, int rope,
                 const float2* __restrict__ tbl)
{
    __shared__ uint32_t sA[2 * ABUF];
    __shared__ uint32_t sB[2 * BBUF];
    gemm_tile(A, W, C, N, K, blockIdx.y * 128, blockIdx.x * 128, rope, tbl, sA, sB);
}

__global__ __launch_bounds__(256)
void gemm_kv_kernel(const float* __restrict__ A,
                    const float* __restrict__ Wk, const float* __restrict__ Wv,
                    float* __restrict__ Ck, float* __restrict__ Cv,
                    int K, const float2* __restrict__ tbl)
{
    __shared__ uint32_t sA[2 * ABUF];
    __shared__ uint32_t sB[2 * BBUF];
    int bx = blockIdx.x;
    if (bx < 4)
        gemm_tile(A, Wk, Ck, 512, K, blockIdx.y * 128, bx * 128, 1, tbl, sA, sB);
    else
        gemm_tile(A, Wv, Cv, 512, K, blockIdx.y * 128, (bx - 4) * 128, 0, tbl, sA, sB);
}

// ---------------------------------------------------------------------------
// Tensor-core causal flash attention (tf32, A-side 2-term split).
// grid=(SEQ/64, QHEADS, BATCH), block=128 (4 warps; warp w owns rows w*16..+15)
// smem (dynamic, 69632B): Ks[64][68] row-major, Vt[68*64] transposed,
//                         Ph/Pl[64][68] P hi/lo tiles.
// ---------------------------------------------------------------------------
#define ATT_STRIDE 68
#define ATT_TILE   (64 * ATT_STRIDE)
#define ATT_SMEM   (4 * ATT_TILE * 4)

__global__ __launch_bounds__(128, 3)
void attn_mma_kernel(const float* __restrict__ Q, const float* __restrict__ Kb,
                     const float* __restrict__ Vb, float* __restrict__ O)
{
    extern __shared__ uint32_t sm[];
    uint32_t* Ks = sm;
    uint32_t* Vt = sm + ATT_TILE;
    uint32_t* Ph = sm + 2 * ATT_TILE;
    uint32_t* Pl = sm + 3 * ATT_TILE;

    const int qt  = blockIdx.x;
    const int h   = blockIdx.y;
    const int b   = blockIdx.z;
    const int kvh = h >> 2;
    const int tid  = threadIdx.x;
    const int lane = tid & 31;
    const int w    = tid >> 5;
    const int g    = lane >> 2;   // group (row within m8)
    const int t    = lane & 3;    // thread in group (k)

    // ---- Q fragments (hi + lo), scaled by 1/sqrt(64) ----
    uint32_t qh[8][4], ql[8][4];
    {
        const float* qbase = Q + (size_t)(b * SEQ + qt * 64 + w * 16) * (QHEADS * HDIM) + h * HDIM;
#pragma unroll
        for (int kt = 0; kt < 8; kt++) {
#pragma unroll
            for (int i = 0; i < 4; i++) {
                int r = g + (i & 1) * 8;
                int c = kt * 8 + t + (i >> 1) * 4;
                float v = qbase[(size_t)r * (QHEADS * HDIM) + c] * 0.125f;
                uint32_t hi = f2tf(v);
                qh[kt][i] = hi;
                ql[kt][i] = f2tf(v - __uint_as_float(hi));
            }
        }
    }

    float o[8][4];
#pragma unroll
    for (int nt = 0; nt < 8; nt++)
#pragma unroll
        for (int i = 0; i < 4; i++) o[nt][i] = 0.f;
    float m0 = -INFINITY, m1 = -INFINITY, l0 = 0.f, l1 = 0.f;

    const size_t kvStride = KVHEADS * HDIM;

    for (int kti = 0; kti <= qt; kti++) {
        __syncthreads();   // previous iteration done reading Ks/Vt
        // ---- stage K (row-major) and V (transposed), tf32-converted ----
        {
            const float* kb = Kb + (size_t)(b * SEQ + kti * 64) * kvStride + kvh * HDIM;
            const float* vb = Vb + (size_t)(b * SEQ + kti * 64) * kvStride + kvh * HDIM;
#pragma unroll
            for (int i2 = 0; i2 < 4; i2++) {
                int idx = tid + i2 * 128;
                int r   = idx & 63;
                int c4  = (idx >> 6) * 8;   // 128 threads: c4 in {0,8,...,56} per i2? -> idx>>6 in 0..7
                // idx ranges 0..511 over i2: idx>>6 in 0..7, c4 = (idx>>6)*8
                float4 kv0 = *(const float4*)(kb + (size_t)r * kvStride + c4);
                float4 kv1 = *(const float4*)(kb + (size_t)r * kvStride + c4 + 4);
                float4 vv0 = *(const float4*)(vb + (size_t)r * kvStride + c4);
                float4 vv1 = *(const float4*)(vb + (size_t)r * kvStride + c4 + 4);
                uint32_t* kd = &Ks[r * ATT_STRIDE + c4];
                kd[0] = f2tf(kv0.x); kd[1] = f2tf(kv0.y); kd[2] = f2tf(kv0.z); kd[3] = f2tf(kv0.w);
                kd[4] = f2tf(kv1.x); kd[5] = f2tf(kv1.y); kd[6] = f2tf(kv1.z); kd[7] = f2tf(kv1.w);
                Vt[(c4 + 0) * ATT_STRIDE + r] = f2tf(vv0.x);
                Vt[(c4 + 1) * ATT_STRIDE + r] = f2tf(vv0.y);
                Vt[(c4 + 2) * ATT_STRIDE + r] = f2tf(vv0.z);
                Vt[(c4 + 3) * ATT_STRIDE + r] = f2tf(vv0.w);
                Vt[(c4 + 4) * ATT_STRIDE + r] = f2tf(vv1.x);
                Vt[(c4 + 5) * ATT_STRIDE + r] = f2tf(vv1.y);
                Vt[(c4 + 6) * ATT_STRIDE + r] = f2tf(vv1.z);
                Vt[(c4 + 7) * ATT_STRIDE + r] = f2tf(vv1.w);
            }
        }
        __syncthreads();

        // ---- S = Q @ K^T  (hi + lo passes share B frags) ----
        float s[8][4];
#pragma unroll
        for (int nt = 0; nt < 8; nt++)
#pragma unroll
            for (int i = 0; i < 4; i++) s[nt][i] = 0.f;
#pragma unroll
        for (int kt = 0; kt < 8; kt++) {
#pragma unroll
            for (int nt = 0; nt < 8; nt++) {
                const uint32_t* kr = &Ks[(nt * 8 + g) * ATT_STRIDE + kt * 8 + t];
                uint32_t bb[2] = { kr[0], kr[4] };
                mma8(s[nt], qh[kt], bb);
                mma8(s[nt], ql[kt], bb);
            }
        }

        // ---- causal mask on diagonal tile ----
        if (kti == qt) {
            int r0 = w * 16 + g, r1 = r0 + 8;
#pragma unroll
            for (int nt = 0; nt < 8; nt++) {
                int c0 = nt * 8 + 2 * t, c1 = c0 + 1;
                if (c0 > r0) s[nt][0] = -INFINITY;
                if (c1 > r0) s[nt][1] = -INFINITY;
                if (c0 > r1) s[nt][2] = -INFINITY;
                if (c1 > r1) s[nt][3] = -INFINITY;
            }
        }

        // ---- online softmax ----
        float cm0 = -INFINITY, cm1 = -INFINITY;
#pragma unroll
        for (int nt = 0; nt < 8; nt++) {
            cm0 = fmaxf(cm0, fmaxf(s[nt][0], s[nt][1]));
            cm1 = fmaxf(cm1, fmaxf(s[nt][2], s[nt][3]));
        }
        cm0 = fmaxf(cm0, __shfl_xor_sync(0xffffffffu, cm0, 1));
        cm0 = fmaxf(cm0, __shfl_xor_sync(0xffffffffu, cm0, 2));
        cm1 = fmaxf(cm1, __shfl_xor_sync(0xffffffffu, cm1, 1));
        cm1 = fmaxf(cm1, __shfl_xor_sync(0xffffffffu, cm1, 2));
        float M0 = fmaxf(m0, cm0), M1 = fmaxf(m1, cm1);
        float sc0 = __expf(m0 - M0), sc1 = __expf(m1 - M1);

        float s0 = 0.f, s1 = 0.f;
        const int prow0 = (w * 16 + g) * ATT_STRIDE;
        const int prow1 = (w * 16 + g + 8) * ATT_STRIDE;
#pragma unroll
        for (int nt = 0; nt < 8; nt++) {
            float p0 = __expf(s[nt][0] - M0);
            float p1 = __expf(s[nt][1] - M0);
            float p2 = __expf(s[nt][2] - M1);
            float p3 = __expf(s[nt][3] - M1);
            s0 += p0 + p1; s1 += p2 + p3;
            uint32_t h0 = f2tf(p0), h1 = f2tf(p1), h2 = f2tf(p2), h3 = f2tf(p3);
            uint32_t L0 = f2tf(p0 - __uint_as_float(h0));
            uint32_t L1 = f2tf(p1 - __uint_as_float(h1));
            uint32_t L2 = f2tf(p2 - __uint_as_float(h2));
            uint32_t L3 = f2tf(p3 - __uint_as_float(h3));
            int co = nt * 8 + 2 * t;
            *(uint2*)&Ph[prow0 + co] = make_uint2(h0, h1);
            *(uint2*)&Ph[prow1 + co] = make_uint2(h2, h3);
            *(uint2*)&Pl[prow0 + co] = make_uint2(L0, L1);
            *(uint2*)&Pl[prow1 + co] = make_uint2(L2, L3);
        }
        s0 += __shfl_xor_sync(0xffffffffu, s0, 1);
        s0 += __shfl_xor_sync(0xffffffffu, s0, 2);
        s1 += __shfl_xor_sync(0xffffffffu, s1, 1);
        s1 += __shfl_xor_sync(0xffffffffu, s1, 2);
        l0 = l0 * sc0 + s0;
        l1 = l1 * sc1 + s1;
#pragma unroll
        for (int nt = 0; nt < 8; nt++) {
            o[nt][0] *= sc0; o[nt][1] *= sc0;
            o[nt][2] *= sc1; o[nt][3] *= sc1;
        }
        m0 = M0; m1 = M1;
        __syncwarp();

        // ---- O += P @ V ----
#pragma unroll
        for (int kt = 0; kt < 8; kt++) {
            int pa = kt * 8 + t;
            uint32_t ah[4] = { Ph[prow0 + pa], Ph[prow1 + pa], Ph[prow0 + pa + 4], Ph[prow1 + pa + 4] };
            uint32_t al[4] = { Pl[prow0 + pa], Pl[prow1 + pa], Pl[prow0 + pa + 4], Pl[prow1 + pa + 4] };
#pragma unroll
            for (int nt = 0; nt < 8; nt++) {
                const uint32_t* vr = &Vt[(nt * 8 + g) * ATT_STRIDE + kt * 8 + t];
                uint32_t bb[2] = { vr[0], vr[4] };
                mma8(o[nt], ah, bb);
                mma8(o[nt], al, bb);
            }
        }
        __syncwarp();
    }

    // ---- finalize ----
    float inv0 = 1.f / l0, inv1 = 1.f / l1;
    float* ob = O + (size_t)(b * SEQ + qt * 64 + w * 16 + g) * DMODEL + h * HDIM;
#pragma unroll
    for (int nt = 0; nt < 8; nt++) {
        int co = nt * 8 + 2 * t;
        *(float2*)(ob + co)              = make_float2(o[nt][0] * inv0, o[nt][1] * inv0);
        *(float2*)(ob + 8 * DMODEL + co) = make_float2(o[nt][2] * inv1, o[nt][3] * inv1);
    }
}

// ---------------------------------------------------------------------------
extern "C" void kernel_launch(void* const* d_in, const int* in_sizes, int n_in,
                              void* d_out, int out_size)
{
    const float* x  = (const float*)d_in[0];
    // d_in[1] = attention_mask: all-true by construction; not read.
    const float* wq = (const float*)d_in[2];
    const float* wk = (const float*)d_in[3];
    const float* wv = (const float*)d_in[4];
    const float* wo = (const float*)d_in[5];
    float* out = (float*)d_out;

    void *pq, *pk, *pv, *pao, *prt;
    cudaGetSymbolAddress(&pq,  g_q);
    cudaGetSymbolAddress(&pk,  g_k);
    cudaGetSymbolAddress(&pv,  g_v);
    cudaGetSymbolAddress(&pao, g_ao);
    cudaGetSymbolAddress(&prt, g_rope);
    float*  qb  = (float*)pq;
    float*  kb  = (float*)pk;
    float*  vb  = (float*)pv;
    float*  aob = (float*)pao;
    float2* tbl = (float2*)prt;

    // RoPE cos/sin table
    rope_table_kernel<<<(SEQ * 32 + 255) / 256, 256>>>(tbl);

    // Projections (RoPE fused into Q and K epilogues)
    {
        dim3 blk(256);
        gemm_kernel<<<dim3(16, 32), blk>>>(x, wq, qb, 2048, 2048, 1, tbl);
        gemm_kv_kernel<<<dim3(8, 32), blk>>>(x, wk, wv, kb, vb, 2048, tbl);
    }

    // Attention (tensor-core)
    {
        static int smem_set = 0;
        if (!smem_set) {
            cudaFuncSetAttribute(attn_mma_kernel,
                                 cudaFuncAttributeMaxDynamicSharedMemorySize, ATT_SMEM);
            smem_set = 1;
        }
        dim3 grid(SEQ / 64, QHEADS, BATCH);
        attn_mma_kernel<<<grid, 128, ATT_SMEM>>>(qb, kb, vb, aob);
    }

    // Output projection
    gemm_kernel<<<dim3(16, 32), 256>>>(aob, wo, out, 2048, 2048, 0, tbl);
}

// round 9
// speedup vs baseline: 4.9619x; 1.2639x over previous
#include <cuda_runtime.h>
#include <math.h>
#include <stdint.h>

#define BATCH   2
#define SEQ     2048
#define DMODEL  2048
#define QHEADS  32
#define KVHEADS 8
#define HDIM    64
#define MROWS   (BATCH * SEQ)   // 4096

// ---------------- scratch (device globals; no runtime allocation) ----------
__device__ float    g_q  [MROWS * (QHEADS  * HDIM)];
__device__ float    g_k  [MROWS * (KVHEADS * HDIM)];
__device__ float    g_v  [MROWS * (KVHEADS * HDIM)];
__device__ float    g_ao [MROWS * DMODEL];
__device__ float2   g_rope[SEQ * 32];
// prepacked bf16x2 K/V fragment tiles (compact 32-word rows):
// [b][kvh][kti(32)][hi:2048 | lo:2048] words
__device__ uint32_t g_kpk[BATCH * KVHEADS * 32 * 4096];
__device__ uint32_t g_vpk[BATCH * KVHEADS * 32 * 4096];

// ---------------------------------------------------------------------------
__global__ void rope_table_kernel(float2* __restrict__ tbl)
{
    int i = blockIdx.x * blockDim.x + threadIdx.x;
    if (i >= SEQ * 32) return;
    int pair = i & 31;
    int pos  = i >> 5;
    double inv = pow(10000.0, -(2.0 * pair) / 64.0);
    double a   = (double)pos * inv;
    tbl[i] = make_float2((float)cos(a), (float)sin(a));
}

// ---------------------------------------------------------------------------
// helpers
// ---------------------------------------------------------------------------
__device__ __forceinline__ uint32_t f2tf(float f)
{
    uint32_t u;
    asm("cvt.rna.tf32.f32 %0, %1;" : "=r"(u) : "f"(f));
    return u;
}
__device__ __forceinline__ uint32_t bfpack(float lo, float hi)
{
    uint32_t d;   // d.hi = first operand, d.lo = second
    asm("cvt.rn.bf16x2.f32 %0, %1, %2;" : "=r"(d) : "f"(hi), "f"(lo));
    return d;
}
__device__ __forceinline__ float bflo(uint32_t w) { return __uint_as_float(w << 16); }
__device__ __forceinline__ float bfhi(uint32_t w) { return __uint_as_float(w & 0xffff0000u); }

__device__ __forceinline__ void mma8(float* c, const uint32_t* a, const uint32_t* b)
{
    asm volatile(
        "mma.sync.aligned.m16n8k8.row.col.f32.tf32.tf32.f32 "
        "{%0,%1,%2,%3}, {%4,%5,%6,%7}, {%8,%9}, {%0,%1,%2,%3};"
        : "+f"(c[0]), "+f"(c[1]), "+f"(c[2]), "+f"(c[3])
        : "r"(a[0]), "r"(a[1]), "r"(a[2]), "r"(a[3]), "r"(b[0]), "r"(b[1]));
}
__device__ __forceinline__ void mma16bf(float* c, const uint32_t* a, uint32_t b0, uint32_t b1)
{
    asm volatile(
        "mma.sync.aligned.m16n8k16.row.col.f32.bf16.bf16.f32 "
        "{%0,%1,%2,%3}, {%4,%5,%6,%7}, {%8,%9}, {%0,%1,%2,%3};"
        : "+f"(c[0]), "+f"(c[1]), "+f"(c[2]), "+f"(c[3])
        : "r"(a[0]), "r"(a[1]), "r"(a[2]), "r"(a[3]), "r"(b0), "r"(b1));
}

// ---------------------------------------------------------------------------
// TF32 tensor-core GEMM (unchanged):
// C[M,N] = A[M,K] @ W[N,K]^T  (+ optional fused RoPE)
// ---------------------------------------------------------------------------
#define AKT  1168
#define AMT  144
#define ARG  36
#define ABUF 2336
#define BKT  1296
#define BNT  80
#define BRG  40
#define BBUF 2592

__device__ __forceinline__ void gemm_tile(
    const float* __restrict__ A, const float* __restrict__ W, float* __restrict__ C,
    int N, int K, int row0, int col0, int rope, const float2* __restrict__ tbl,
    uint32_t* sA, uint32_t* sB)
{
    const int tid  = threadIdx.x;
    const int lane = tid & 31;
    const int wid  = tid >> 5;
    const int wm   = wid & 1;
    const int wn   = wid >> 1;

    int a_st[2], b_st[2], a_m[2], ab_k4[2], b_n[2];
#pragma unroll
    for (int t = 0; t < 2; t++) {
        int idx = tid + t * 256;
        int m   = idx >> 2;
        int k4  = (idx & 3) * 4;
        a_m[t] = m; b_n[t] = m; ab_k4[t] = k4;
        int kt   = k4 >> 3;
        int kin0 = k4 & 7;
        int arg  = ((kin0 >= 4) ? 2 : 0) | (((m & 15) >= 8) ? 1 : 0);
        a_st[t]  = kt * AKT + (m >> 4) * AMT + arg * ARG + (m & 7) * 4;
        int brg  = (kin0 >= 4) ? 1 : 0;
        b_st[t]  = kt * BKT + (m >> 3) * BNT + brg * BRG + (m & 7) * 4;
    }

    float acc[4][4][4];
#pragma unroll
    for (int i = 0; i < 4; i++)
#pragma unroll
        for (int j = 0; j < 4; j++)
#pragma unroll
            for (int r = 0; r < 4; r++) acc[i][j][r] = 0.f;

    float4 ar[2], br[2];
#pragma unroll
    for (int t = 0; t < 2; t++) {
        ar[t] = *(const float4*)(A + (size_t)(row0 + a_m[t]) * K + ab_k4[t]);
        br[t] = *(const float4*)(W + (size_t)(col0 + b_n[t]) * K + ab_k4[t]);
    }
#pragma unroll
    for (int t = 0; t < 2; t++) {
        uint4 av = make_uint4(f2tf(ar[t].x), f2tf(ar[t].y), f2tf(ar[t].z), f2tf(ar[t].w));
        uint4 bv = make_uint4(f2tf(br[t].x), f2tf(br[t].y), f2tf(br[t].z), f2tf(br[t].w));
        *(uint4*)(sA + a_st[t]) = av;
        *(uint4*)(sB + b_st[t]) = bv;
    }
    __syncthreads();

    int buf = 0;
    for (int k0 = 16; ; k0 += 16) {
        const bool more = (k0 < K);
        if (more) {
#pragma unroll
            for (int t = 0; t < 2; t++) {
                ar[t] = *(const float4*)(A + (size_t)(row0 + a_m[t]) * K + k0 + ab_k4[t]);
                br[t] = *(const float4*)(W + (size_t)(col0 + b_n[t]) * K + k0 + ab_k4[t]);
            }
        }
        const uint32_t* Ab = sA + buf * ABUF;
        const uint32_t* Bb = sB + buf * BBUF;
#pragma unroll
        for (int kt = 0; kt < 2; kt++) {
            uint32_t af[4][4], bf[4][2];
#pragma unroll
            for (int mt = 0; mt < 4; mt++) {
                int base = kt * AKT + (wm * 4 + mt) * AMT + lane;
#pragma unroll
                for (int rg = 0; rg < 4; rg++) af[mt][rg] = Ab[base + rg * ARG];
            }
#pragma unroll
            for (int nt = 0; nt < 4; nt++) {
                int base = kt * BKT + (wn * 4 + nt) * BNT + lane;
#pragma unroll
                for (int rg = 0; rg < 2; rg++) bf[nt][rg] = Bb[base + rg * BRG];
            }
#pragma unroll
            for (int mt = 0; mt < 4; mt++)
#pragma unroll
                for (int nt = 0; nt < 4; nt++)
                    mma8(acc[mt][nt], af[mt], bf[nt]);
        }
        if (!more) break;
        uint32_t* An = sA + (buf ^ 1) * ABUF;
        uint32_t* Bn = sB + (buf ^ 1) * BBUF;
#pragma unroll
        for (int t = 0; t < 2; t++) {
            uint4 av = make_uint4(f2tf(ar[t].x), f2tf(ar[t].y), f2tf(ar[t].z), f2tf(ar[t].w));
            uint4 bv = make_uint4(f2tf(br[t].x), f2tf(br[t].y), f2tf(br[t].z), f2tf(br[t].w));
            *(uint4*)(An + a_st[t]) = av;
            *(uint4*)(Bn + b_st[t]) = bv;
        }
        __syncthreads();
        buf ^= 1;
    }

    const int r_base = row0 + wm * 64 + (lane >> 2);
    const int c_base = col0 + wn * 32 + (lane & 3) * 2;
#pragma unroll
    for (int mt = 0; mt < 4; mt++) {
#pragma unroll
        for (int nt = 0; nt < 4; nt++) {
            int r  = r_base + mt * 16;
            int cc = c_base + nt * 8;
            float v0 = acc[mt][nt][0], v1 = acc[mt][nt][1];
            float v2 = acc[mt][nt][2], v3 = acc[mt][nt][3];
            if (rope) {
                int pair = (cc & 63) >> 1;
                float2 cs1 = tbl[(r       & (SEQ - 1)) * 32 + pair];
                float2 cs2 = tbl[((r + 8) & (SEQ - 1)) * 32 + pair];
                float o0 = v0 * cs1.x - v1 * cs1.y;
                float o1 = v1 * cs1.x + v0 * cs1.y;
                float o2 = v2 * cs2.x - v3 * cs2.y;
                float o3 = v3 * cs2.x + v2 * cs2.y;
                v0 = o0; v1 = o1; v2 = o2; v3 = o3;
            }
            *(float2*)&C[(size_t)r * N + cc]       = make_float2(v0, v1);
            *(float2*)&C[(size_t)(r + 8) * N + cc] = make_float2(v2, v3);
        }
    }
}

__global__ __launch_bounds__(256)
void gemm_kernel(const float* __restrict__ A, const float* __restrict__ W,
                 float* __restrict__ C, int N, int K, int rope,
                 const float2* __restrict__ tbl)
{
    __shared__ uint32_t sA[2 * ABUF];
    __shared__ uint32_t sB[2 * BBUF];
    gemm_tile(A, W, C, N, K, blockIdx.y * 128, blockIdx.x * 128, rope, tbl, sA, sB);
}

__global__ __launch_bounds__(256)
void gemm_kv_kernel(const float* __restrict__ A,
                    const float* __restrict__ Wk, const float* __restrict__ Wv,
                    float* __restrict__ Ck, float* __restrict__ Cv,
                    int K, const float2* __restrict__ tbl)
{
    __shared__ uint32_t sA[2 * ABUF];
    __shared__ uint32_t sB[2 * BBUF];
    int bx = blockIdx.x;
    if (bx < 4)
        gemm_tile(A, Wk, Ck, 512, K, blockIdx.y * 128, bx * 128, 1, tbl, sA, sB);
    else
        gemm_tile(A, Wv, Cv, 512, K, blockIdx.y * 128, (bx - 4) * 128, 0, tbl, sA, sB);
}

// ---------------------------------------------------------------------------
// Prepack K,V into bf16x2 hi/lo fragment-order tiles (compact 32-word rows).
// Tile (b,kvh,kti): word w = n*32 + j,  j = kt*8 + t*2 + hi:
//   K: pack(K[n][kt*16+2t+8hi], K[n][..+1]);  V: pack(V[key0][n], V[key0+1][n])
// hi sub-tile at [0,2048), lo residual sub-tile at [2048,4096).
// ---------------------------------------------------------------------------
__global__ __launch_bounds__(256)
void prepack_kv_kernel(const float* __restrict__ K, const float* __restrict__ V,
                       uint32_t* __restrict__ kpk, uint32_t* __restrict__ vpk)
{
    const int kti = blockIdx.x, kvh = blockIdx.y, b = blockIdx.z;
    const size_t tile = ((size_t)(b * KVHEADS + kvh) * 32 + kti) * 4096;
    uint32_t* kd = kpk + tile;
    uint32_t* vd = vpk + tile;
    const size_t kvStride = KVHEADS * HDIM;

    for (int w = threadIdx.x; w < 2048; w += 256) {
        int n  = w >> 5, j = w & 31;
        int kt = j >> 3, jj = j & 7;
        int t  = jj >> 1, hi = jj & 1;
        int d0 = kt * 16 + 2 * t + 8 * hi;

        const float* krow = K + (size_t)(b * SEQ + kti * 64 + n) * kvStride + kvh * HDIM;
        float k0 = krow[d0], k1 = krow[d0 + 1];
        uint32_t wh = bfpack(k0, k1);
        uint32_t wl = bfpack(k0 - bflo(wh), k1 - bfhi(wh));
        kd[w] = wh; kd[2048 + w] = wl;

        int key0 = kti * 64 + d0;
        const float* vb = V + (size_t)(b * SEQ + key0) * kvStride + kvh * HDIM + n;
        float v0 = vb[0], v1 = vb[kvStride];
        uint32_t uh = bfpack(v0, v1);
        uint32_t ul = bfpack(v0 - bflo(uh), v1 - bfhi(uh));
        vd[w] = uh; vd[2048 + w] = ul;
    }
}

// ---------------------------------------------------------------------------
// bf16 tensor-core causal flash attention (full 2-term on Q,K,P,V).
// grid=(SEQ/128, QHEADS, BATCH), block=128 (4 warps x 32 q-rows).
// Double-buffered cp.async staging; smem rows padded to stride 40
// (conflict-free 64-bit fragment loads), padding inserted at copy time.
// ---------------------------------------------------------------------------
#define AT_STRIDE 40
#define AT_SUB    2560
#define AT_BUF    10240
#define AT_SMEM   (2 * AT_BUF * 4)   // 81920 B

__device__ __forceinline__ void cpasync16(uint32_t dst, const void* src)
{
    asm volatile("cp.async.cg.shared.global [%0], [%1], 16;" :: "r"(dst), "l"(src));
}

__global__ __launch_bounds__(128, 2)
void attn_bf16_kernel(const float* __restrict__ Q,
                      const uint32_t* __restrict__ kpk,
                      const uint32_t* __restrict__ vpk,
                      float* __restrict__ O)
{
    extern __shared__ uint32_t sm[];
    uint32_t smem_u32;
    {
        uint64_t a64;
        asm("cvta.to.shared.u64 %0, %1;" : "=l"(a64) : "l"(sm));
        smem_u32 = (uint32_t)a64;
    }

    const int qt  = (SEQ / 128 - 1) - blockIdx.x;   // heavy tiles first
    const int h   = blockIdx.y;
    const int b   = blockIdx.z;
    const int kvh = h >> 2;
    const int tid  = threadIdx.x;
    const int lane = tid & 31;
    const int w    = tid >> 5;
    const int g    = lane >> 2;
    const int t    = lane & 3;

    // ---- Q fragments (bf16x2 hi/lo), scaled by 1/8 ----
    uint32_t qh[2][4][4], ql[2][4][4];
    {
        const float* qb = Q + (size_t)(b * SEQ + qt * 128 + w * 32) * DMODEL + h * HDIM;
#pragma unroll
        for (int mt = 0; mt < 2; mt++) {
#pragma unroll
            for (int kt = 0; kt < 4; kt++) {
                int r0 = mt * 16 + g, r1 = r0 + 8;
                int c0 = kt * 16 + 2 * t, c2 = c0 + 8;
                float2 x0 = *(const float2*)(qb + (size_t)r0 * DMODEL + c0);
                float2 x1 = *(const float2*)(qb + (size_t)r1 * DMODEL + c0);
                float2 x2 = *(const float2*)(qb + (size_t)r0 * DMODEL + c2);
                float2 x3 = *(const float2*)(qb + (size_t)r1 * DMODEL + c2);
                x0.x *= 0.125f; x0.y *= 0.125f; x1.x *= 0.125f; x1.y *= 0.125f;
                x2.x *= 0.125f; x2.y *= 0.125f; x3.x *= 0.125f; x3.y *= 0.125f;
                uint32_t h0 = bfpack(x0.x, x0.y), h1 = bfpack(x1.x, x1.y);
                uint32_t h2 = bfpack(x2.x, x2.y), h3 = bfpack(x3.x, x3.y);
                qh[mt][kt][0] = h0; qh[mt][kt][1] = h1; qh[mt][kt][2] = h2; qh[mt][kt][3] = h3;
                ql[mt][kt][0] = bfpack(x0.x - bflo(h0), x0.y - bfhi(h0));
                ql[mt][kt][1] = bfpack(x1.x - bflo(h1), x1.y - bfhi(h1));
                ql[mt][kt][2] = bfpack(x2.x - bflo(h2), x2.y - bfhi(h2));
                ql[mt][kt][3] = bfpack(x3.x - bflo(h3), x3.y - bfhi(h3));
            }
        }
    }

    float o[2][8][4];
#pragma unroll
    for (int mt = 0; mt < 2; mt++)
#pragma unroll
        for (int nt = 0; nt < 8; nt++)
#pragma unroll
            for (int i = 0; i < 4; i++) o[mt][nt][i] = 0.f;
    float mrow[2][2] = { {-INFINITY, -INFINITY}, {-INFINITY, -INFINITY} };
    float lrow[2][2] = { {0.f, 0.f}, {0.f, 0.f} };

    const int last = 2 * qt + 1;
    const uint32_t* kbase_g = kpk + (size_t)(b * KVHEADS + kvh) * 32 * 4096;
    const uint32_t* vbase_g = vpk + (size_t)(b * KVHEADS + kvh) * 32 * 4096;

    // stage: compact global rows (32 w) -> padded smem rows (40 w)
    auto stage = [&](int kti, int buf) {
        uint32_t dst = smem_u32 + buf * (AT_BUF * 4);
        const uint32_t* ks = kbase_g + (size_t)kti * 4096;
        const uint32_t* vs = vbase_g + (size_t)kti * 4096;
#pragma unroll
        for (int i = 0; i < 8; i++) {
            int c   = tid + i * 128;          // 0..1023 chunks of 16B
            int sub = c >> 9;                 // 0 = hi, 1 = lo
            int r   = (c >> 3) & 63;
            int off = c & 7;
            uint32_t d = dst + (sub * AT_SUB + r * AT_STRIDE + off * 4) * 4;
            cpasync16(d, ks + (size_t)c * 4);
            cpasync16(d + 2 * AT_SUB * 4, vs + (size_t)c * 4);
        }
        asm volatile("cp.async.commit_group;" ::: "memory");
    };

    stage(0, 0);

    for (int kti = 0; kti <= last; kti++) {
        const int buf = kti & 1;
        if (kti < last) {
            __syncthreads();                // prior compute on buf^1 finished
            stage(kti + 1, buf ^ 1);
            asm volatile("cp.async.wait_group 1;" ::: "memory");
        } else {
            asm volatile("cp.async.wait_group 0;" ::: "memory");
        }
        __syncthreads();

        const uint32_t* sKh = sm + buf * AT_BUF;
        const uint32_t* sKl = sKh + AT_SUB;
        const uint32_t* sVh = sKh + 2 * AT_SUB;
        const uint32_t* sVl = sKh + 3 * AT_SUB;

        const int kb = kti * 64;
        bool act[2];
        act[0] = kb <= qt * 128 + w * 32 + 15;
        act[1] = kb <= qt * 128 + w * 32 + 31;
        if (!act[1]) continue;

        // ---- S = Q @ K^T  (QhKh + QlKh + QhKl) ----
        float s2[2][8][4];
#pragma unroll
        for (int mt = 0; mt < 2; mt++)
#pragma unroll
            for (int nt = 0; nt < 8; nt++)
#pragma unroll
                for (int i = 0; i < 4; i++) s2[mt][nt][i] = 0.f;

#pragma unroll
        for (int kt = 0; kt < 4; kt++) {
#pragma unroll
            for (int nt = 0; nt < 8; nt++) {
                uint2 bh = *(const uint2*)&sKh[(nt * 8 + g) * AT_STRIDE + kt * 8 + t * 2];
                uint2 bl = *(const uint2*)&sKl[(nt * 8 + g) * AT_STRIDE + kt * 8 + t * 2];
#pragma unroll
                for (int mt = 0; mt < 2; mt++) {
                    if (mt == 0 && !act[0]) continue;
                    mma16bf(s2[mt][nt], qh[mt][kt], bh.x, bh.y);
                    mma16bf(s2[mt][nt], ql[mt][kt], bh.x, bh.y);
                    mma16bf(s2[mt][nt], qh[mt][kt], bl.x, bl.y);
                }
            }
        }

        // ---- mask + online softmax + pack P (hi and residual lo) ----
        uint32_t ph2[2][8][2], pl2[2][8][2];
#pragma unroll
        for (int mt = 0; mt < 2; mt++) {
            if (mt == 0 && !act[0]) continue;
            int r0g = qt * 128 + w * 32 + mt * 16 + g;
            int r1g = r0g + 8;
            if (kb + 63 > r0g) {
#pragma unroll
                for (int nt = 0; nt < 8; nt++) {
                    int c0 = kb + nt * 8 + 2 * t, c1 = c0 + 1;
                    if (c0 > r0g) s2[mt][nt][0] = -INFINITY;
                    if (c1 > r0g) s2[mt][nt][1] = -INFINITY;
                    if (c0 > r1g) s2[mt][nt][2] = -INFINITY;
                    if (c1 > r1g) s2[mt][nt][3] = -INFINITY;
                }
            }
            float cm0 = -INFINITY, cm1 = -INFINITY;
#pragma unroll
            for (int nt = 0; nt < 8; nt++) {
                cm0 = fmaxf(cm0, fmaxf(s2[mt][nt][0], s2[mt][nt][1]));
                cm1 = fmaxf(cm1, fmaxf(s2[mt][nt][2], s2[mt][nt][3]));
            }
            cm0 = fmaxf(cm0, __shfl_xor_sync(0xffffffffu, cm0, 1));
            cm0 = fmaxf(cm0, __shfl_xor_sync(0xffffffffu, cm0, 2));
            cm1 = fmaxf(cm1, __shfl_xor_sync(0xffffffffu, cm1, 1));
            cm1 = fmaxf(cm1, __shfl_xor_sync(0xffffffffu, cm1, 2));
            float M0 = fmaxf(mrow[mt][0], cm0), M1 = fmaxf(mrow[mt][1], cm1);
            float sc0 = __expf(mrow[mt][0] - M0), sc1 = __expf(mrow[mt][1] - M1);
            float sum0 = 0.f, sum1 = 0.f;
#pragma unroll
            for (int nt = 0; nt < 8; nt++) {
                float p0 = __expf(s2[mt][nt][0] - M0);
                float p1 = __expf(s2[mt][nt][1] - M0);
                float p2 = __expf(s2[mt][nt][2] - M1);
                float p3 = __expf(s2[mt][nt][3] - M1);
                sum0 += p0 + p1; sum1 += p2 + p3;
                uint32_t w0 = bfpack(p0, p1), w1 = bfpack(p2, p3);
                ph2[mt][nt][0] = w0;
                ph2[mt][nt][1] = w1;
                pl2[mt][nt][0] = bfpack(p0 - bflo(w0), p1 - bfhi(w0));
                pl2[mt][nt][1] = bfpack(p2 - bflo(w1), p3 - bfhi(w1));
            }
            sum0 += __shfl_xor_sync(0xffffffffu, sum0, 1);
            sum0 += __shfl_xor_sync(0xffffffffu, sum0, 2);
            sum1 += __shfl_xor_sync(0xffffffffu, sum1, 1);
            sum1 += __shfl_xor_sync(0xffffffffu, sum1, 2);
            lrow[mt][0] = lrow[mt][0] * sc0 + sum0;
            lrow[mt][1] = lrow[mt][1] * sc1 + sum1;
#pragma unroll
            for (int nt = 0; nt < 8; nt++) {
                o[mt][nt][0] *= sc0; o[mt][nt][1] *= sc0;
                o[mt][nt][2] *= sc1; o[mt][nt][3] *= sc1;
            }
            mrow[mt][0] = M0; mrow[mt][1] = M1;
        }

        // ---- O += P @ V  (PhVh + PhVl + PlVh) ----
#pragma unroll
        for (int kt = 0; kt < 4; kt++) {
#pragma unroll
            for (int nt = 0; nt < 8; nt++) {
                uint2 bh = *(const uint2*)&sVh[(nt * 8 + g) * AT_STRIDE + kt * 8 + t * 2];
                uint2 bl = *(const uint2*)&sVl[(nt * 8 + g) * AT_STRIDE + kt * 8 + t * 2];
#pragma unroll
                for (int mt = 0; mt < 2; mt++) {
                    if (mt == 0 && !act[0]) continue;
                    uint32_t ah[4] = { ph2[mt][2 * kt][0], ph2[mt][2 * kt][1],
                                       ph2[mt][2 * kt + 1][0], ph2[mt][2 * kt + 1][1] };
                    uint32_t al[4] = { pl2[mt][2 * kt][0], pl2[mt][2 * kt][1],
                                       pl2[mt][2 * kt + 1][0], pl2[mt][2 * kt + 1][1] };
                    mma16bf(o[mt][nt], ah, bh.x, bh.y);
                    mma16bf(o[mt][nt], ah, bl.x, bl.y);
                    mma16bf(o[mt][nt], al, bh.x, bh.y);
                }
            }
        }
    }

    // ---- finalize ----
#pragma unroll
    for (int mt = 0; mt < 2; mt++) {
        float inv0 = 1.f / lrow[mt][0], inv1 = 1.f / lrow[mt][1];
        float* ob = O + (size_t)(b * SEQ + qt * 128 + w * 32 + mt * 16 + g) * DMODEL + h * HDIM;
#pragma unroll
        for (int nt = 0; nt < 8; nt++) {
            int co = nt * 8 + 2 * t;
            *(float2*)(ob + co)              = make_float2(o[mt][nt][0] * inv0, o[mt][nt][1] * inv0);
            *(float2*)(ob + 8 * DMODEL + co) = make_float2(o[mt][nt][2] * inv1, o[mt][nt][3] * inv1);
        }
    }
}

// ---------------------------------------------------------------------------
extern "C" void kernel_launch(void* const* d_in, const int* in_sizes, int n_in,
                              void* d_out, int out_size)
{
    const float* x  = (const float*)d_in[0];
    // d_in[1] = attention_mask: all-true by construction; not read.
    const float* wq = (const float*)d_in[2];
    const float* wk = (const float*)d_in[3];
    const float* wv = (const float*)d_in[4];
    const float* wo = (const float*)d_in[5];
    float* out = (float*)d_out;

    void *pq, *pk, *pv, *pao, *prt, *pkp, *pvp;
    cudaGetSymbolAddress(&pq,  g_q);
    cudaGetSymbolAddress(&pk,  g_k);
    cudaGetSymbolAddress(&pv,  g_v);
    cudaGetSymbolAddress(&pao, g_ao);
    cudaGetSymbolAddress(&prt, g_rope);
    cudaGetSymbolAddress(&pkp, g_kpk);
    cudaGetSymbolAddress(&pvp, g_vpk);
    float*    qb  = (float*)pq;
    float*    kb  = (float*)pk;
    float*    vb  = (float*)pv;
    float*    aob = (float*)pao;
    float2*   tbl = (float2*)prt;
    uint32_t* kpk = (uint32_t*)pkp;
    uint32_t* vpk = (uint32_t*)pvp;

    // RoPE cos/sin table
    rope_table_kernel<<<(SEQ * 32 + 255) / 256, 256>>>(tbl);

    // Projections (RoPE fused into Q and K epilogues)
    {
        dim3 blk(256);
        gemm_kernel<<<dim3(16, 32), blk>>>(x, wq, qb, 2048, 2048, 1, tbl);
        gemm_kv_kernel<<<dim3(8, 32), blk>>>(x, wk, wv, kb, vb, 2048, tbl);
    }

    // Prepack K/V into bf16x2 fragment tiles
    prepack_kv_kernel<<<dim3(32, KVHEADS, BATCH), 256>>>(kb, vb, kpk, vpk);

    // Attention (bf16 tensor-core, 2-term everywhere, double-buffered cp.async)
    {
        static int smem_set = 0;
        if (!smem_set) {
            cudaFuncSetAttribute(attn_bf16_kernel,
                                 cudaFuncAttributeMaxDynamicSharedMemorySize, AT_SMEM);
            smem_set = 1;
        }
        dim3 grid(SEQ / 128, QHEADS, BATCH);
        attn_bf16_kernel<<<grid, 128, AT_SMEM>>>(qb, kpk, vpk, aob);
    }

    // Output projection
    gemm_kernel<<<dim3(16, 32), 256>>>(aob, wo, out, 2048, 2048, 0, tbl);
}

// round 13
// speedup vs baseline: 5.6985x; 1.1485x over previous
#include <cuda_runtime.h>
#include <math.h>
#include <stdint.h>

#define BATCH   2
#define SEQ     2048
#define DMODEL  2048
#define QHEADS  32
#define KVHEADS 8
#define HDIM    64
#define MROWS   (BATCH * SEQ)   // 4096

// ---------------- scratch (device globals; no runtime allocation) ----------
__device__ float    g_q  [MROWS * (QHEADS  * HDIM)];
__device__ float    g_k  [MROWS * (KVHEADS * HDIM)];
__device__ float    g_v  [MROWS * (KVHEADS * HDIM)];
__device__ float    g_ao [MROWS * DMODEL];
__device__ float2   g_rope[SEQ * 32];
__device__ uint32_t g_kpk[BATCH * KVHEADS * 32 * 4096];
__device__ uint32_t g_vpk[BATCH * KVHEADS * 32 * 4096];
// tf32 fragment-packed GEMM operands
__device__ uint32_t g_xpk [32 * 128 * 2048];           // x   (A) 32 mtiles
__device__ uint32_t g_aopk[32 * 128 * 2048];           // ao  (A)
__device__ uint32_t g_wpk [20 * 128 * 4096];           // wq(0-7) wk(8-9) wv(10-11) wo(12-19)

// ---------------------------------------------------------------------------
__global__ void rope_table_kernel(float2* __restrict__ tbl)
{
    int i = blockIdx.x * blockDim.x + threadIdx.x;
    if (i >= SEQ * 32) return;
    int pair = i & 31;
    int pos  = i >> 5;
    double inv = pow(10000.0, -(2.0 * pair) / 64.0);
    double a   = (double)pos * inv;
    tbl[i] = make_float2((float)cos(a), (float)sin(a));
}

// ---------------------------------------------------------------------------
// helpers
// ---------------------------------------------------------------------------
__device__ __forceinline__ uint32_t f2tf(float f)
{
    uint32_t u;
    asm("cvt.rna.tf32.f32 %0, %1;" : "=r"(u) : "f"(f));
    return u;
}
__device__ __forceinline__ uint32_t bfpack(float lo, float hi)
{
    uint32_t d;
    asm("cvt.rn.bf16x2.f32 %0, %1, %2;" : "=r"(d) : "f"(hi), "f"(lo));
    return d;
}
__device__ __forceinline__ float bflo(uint32_t w) { return __uint_as_float(w << 16); }
__device__ __forceinline__ float bfhi(uint32_t w) { return __uint_as_float(w & 0xffff0000u); }

__device__ __forceinline__ void mma8(float* c, const uint32_t* a, const uint32_t* b)
{
    asm volatile(
        "mma.sync.aligned.m16n8k8.row.col.f32.tf32.tf32.f32 "
        "{%0,%1,%2,%3}, {%4,%5,%6,%7}, {%8,%9}, {%0,%1,%2,%3};"
        : "+f"(c[0]), "+f"(c[1]), "+f"(c[2]), "+f"(c[3])
        : "r"(a[0]), "r"(a[1]), "r"(a[2]), "r"(a[3]), "r"(b[0]), "r"(b[1]));
}
__device__ __forceinline__ void mma16bf(float* c, const uint32_t* a, uint32_t b0, uint32_t b1)
{
    asm volatile(
        "mma.sync.aligned.m16n8k16.row.col.f32.bf16.bf16.f32 "
        "{%0,%1,%2,%3}, {%4,%5,%6,%7}, {%8,%9}, {%0,%1,%2,%3};"
        : "+f"(c[0]), "+f"(c[1]), "+f"(c[2]), "+f"(c[3])
        : "r"(a[0]), "r"(a[1]), "r"(a[2]), "r"(a[3]), "r"(b0), "r"(b1));
}
__device__ __forceinline__ void cpasync16(uint32_t dst, const void* src)
{
    asm volatile("cp.async.cg.shared.global [%0], [%1], 16;" :: "r"(dst), "l"(src));
}

// ---------------------------------------------------------------------------
// Prepack A-operand (M x 2048 fp32) into tf32 fragment order:
// word((mtile,ktile),(mt,k8,lane,rg)) ; rg = k4*2 + hi ; lane = g*4 + t
// ---------------------------------------------------------------------------
__global__ __launch_bounds__(256)
void prepack_A_kernel(const float* __restrict__ src, uint32_t* __restrict__ dst)
{
    const int ktile = blockIdx.x, mtile = blockIdx.y;
    uint32_t* d = dst + ((size_t)mtile * 128 + ktile) * 2048;
    for (int w = threadIdx.x; w < 2048; w += 256) {
        int mt = w >> 8, k8 = (w >> 7) & 1, lane = (w >> 2) & 31, rg = w & 3;
        int g = lane >> 2, t = lane & 3, k4 = rg >> 1, hi = rg & 1;
        int m = mtile * 128 + mt * 16 + hi * 8 + g;
        int k = ktile * 16 + k8 * 8 + k4 * 4 + t;
        d[w] = f2tf(src[(size_t)m * 2048 + k]);
    }
}

// B-operand (N x 2048 fp32, row n = output col) into fragment order:
// word((ntile,ktile),(nt,k8,lane,b)) ; lane = g*4 + t (g = n&7) ; b = k4
// ---------------------------------------------------------------------------
__global__ __launch_bounds__(256)
void prepack_B_kernel(const float* __restrict__ src, uint32_t* __restrict__ dst, int base)
{
    const int ktile = blockIdx.x, n256 = blockIdx.y;
    uint32_t* d = dst + ((size_t)(base + n256) * 128 + ktile) * 4096;
    for (int w = threadIdx.x; w < 4096; w += 256) {
        int nt = w >> 7, k8 = (w >> 6) & 1, lane = (w >> 1) & 31, b = w & 1;
        int g = lane >> 2, t = lane & 3;
        int n = n256 * 256 + nt * 8 + g;
        int k = ktile * 16 + k8 * 8 + b * 4 + t;
        d[w] = f2tf(src[(size_t)n * 2048 + k]);
    }
}

// ---------------------------------------------------------------------------
// tf32 mma.sync GEMM on prepacked operands.
// CTA 128x256, 8 warps (wm 2 x wn 4), warp tile 64x64, K-slab 32, dbl-buffered
// cp.async verbatim staging; fragment loads are LDS.128 (A) / LDS.64 (B).
// ---------------------------------------------------------------------------
#define G2_BUFW 12288                 // words/buffer: A 4096 + B 8192
#define G2_SMEM (2 * G2_BUFW * 4)     // 98304 B

__device__ __forceinline__ void gemm2_tile(
    const uint32_t* __restrict__ Apk, const uint32_t* __restrict__ Bpk,
    float* __restrict__ C, int ldc, int mtile, int col0, int rope,
    const float2* __restrict__ tbl)
{
    extern __shared__ uint32_t sm[];
    uint32_t smem_u32;
    { uint64_t a; asm("cvta.to.shared.u64 %0, %1;" : "=l"(a) : "l"(sm)); smem_u32 = (uint32_t)a; }

    const int tid = threadIdx.x, lane = tid & 31, w = tid >> 5;
    const int wm = w & 1, wn = w >> 1;
    const int g = lane >> 2, t = lane & 3;

    float acc[4][8][4];
#pragma unroll
    for (int mt = 0; mt < 4; mt++)
#pragma unroll
        for (int nt = 0; nt < 8; nt++)
#pragma unroll
            for (int i = 0; i < 4; i++) acc[mt][nt][i] = 0.f;

    const uint32_t* Aslab = Apk + (size_t)mtile * 128 * 2048;

    auto stage = [&](int s, int buf) {
        uint32_t dst = smem_u32 + (uint32_t)buf * (G2_BUFW * 4);
        const uint32_t* as = Aslab + (size_t)(s * 2) * 2048;   // 4096 w contiguous
        const uint32_t* bs = Bpk   + (size_t)(s * 2) * 4096;   // 8192 w contiguous
#pragma unroll
        for (int i = 0; i < 4; i++) {
            int c = tid + i * 256;
            cpasync16(dst + c * 16, as + (size_t)c * 4);
        }
#pragma unroll
        for (int i = 0; i < 8; i++) {
            int c = tid + i * 256;
            cpasync16(dst + 16384 + c * 16, bs + (size_t)c * 4);
        }
        asm volatile("cp.async.commit_group;" ::: "memory");
    };

    stage(0, 0);

    for (int s = 0; s < 64; s++) {
        const int buf = s & 1;
        if (s < 63) {
            __syncthreads();
            stage(s + 1, buf ^ 1);
            asm volatile("cp.async.wait_group 1;" ::: "memory");
        } else {
            asm volatile("cp.async.wait_group 0;" ::: "memory");
        }
        __syncthreads();

        const uint32_t* bA = sm + buf * G2_BUFW;
        const uint32_t* bB = bA + 4096;
#pragma unroll
        for (int ktl = 0; ktl < 2; ktl++) {
#pragma unroll
            for (int k8 = 0; k8 < 2; k8++) {
                uint4 af[4];
                uint2 bf[8];
#pragma unroll
                for (int mt = 0; mt < 4; mt++)
                    af[mt] = *(const uint4*)&bA[ktl * 2048 + (wm * 4 + mt) * 256 + k8 * 128 + lane * 4];
#pragma unroll
                for (int nt = 0; nt < 8; nt++)
                    bf[nt] = *(const uint2*)&bB[ktl * 4096 + (wn * 8 + nt) * 128 + k8 * 64 + lane * 2];
#pragma unroll
                for (int mt = 0; mt < 4; mt++)
#pragma unroll
                    for (int nt = 0; nt < 8; nt++)
                        mma8(acc[mt][nt], (const uint32_t*)&af[mt], (const uint32_t*)&bf[nt]);
            }
        }
    }

    // ---- epilogue (+ optional fused RoPE on interleaved pairs) ----
    const int row0 = mtile * 128 + wm * 64;
#pragma unroll
    for (int mt = 0; mt < 4; mt++) {
        int r0 = row0 + mt * 16 + g;
#pragma unroll
        for (int nt = 0; nt < 8; nt++) {
            int c = col0 + wn * 64 + nt * 8 + 2 * t;
            float v0 = acc[mt][nt][0], v1 = acc[mt][nt][1];
            float v2 = acc[mt][nt][2], v3 = acc[mt][nt][3];
            if (rope) {
                int pair = (c & 63) >> 1;
                float2 cs1 = tbl[(r0       & (SEQ - 1)) * 32 + pair];
                float2 cs2 = tbl[((r0 + 8) & (SEQ - 1)) * 32 + pair];
                float o0 = v0 * cs1.x - v1 * cs1.y;
                float o1 = v1 * cs1.x + v0 * cs1.y;
                float o2 = v2 * cs2.x - v3 * cs2.y;
                float o3 = v3 * cs2.x + v2 * cs2.y;
                v0 = o0; v1 = o1; v2 = o2; v3 = o3;
            }
            *(float2*)&C[(size_t)r0 * ldc + c]       = make_float2(v0, v1);
            *(float2*)&C[(size_t)(r0 + 8) * ldc + c] = make_float2(v2, v3);
        }
    }
}

__global__ __launch_bounds__(256, 1)
void qkv_gemm2_kernel(const uint32_t* __restrict__ xpk,
                      const uint32_t* __restrict__ wpk,
                      float* __restrict__ qb, float* __restrict__ kb,
                      float* __restrict__ vb, const float2* __restrict__ tbl)
{
    const int bx = blockIdx.x;
    float* C; int ldc, col0, rope;
    if (bx < 8)       { C = qb; ldc = 2048; col0 = bx * 256;        rope = 1; }
    else if (bx < 10) { C = kb; ldc = 512;  col0 = (bx - 8) * 256;  rope = 1; }
    else              { C = vb; ldc = 512;  col0 = (bx - 10) * 256; rope = 0; }
    gemm2_tile(xpk, wpk + (size_t)bx * 128 * 4096, C, ldc, blockIdx.y, col0, rope, tbl);
}

__global__ __launch_bounds__(256, 1)
void o_gemm2_kernel(const uint32_t* __restrict__ aopk,
                    const uint32_t* __restrict__ wpk,
                    float* __restrict__ out, const float2* __restrict__ tbl)
{
    const int bx = blockIdx.x;
    gemm2_tile(aopk, wpk + (size_t)(12 + bx) * 128 * 4096, out, 2048,
               blockIdx.y, bx * 256, 0, tbl);
}

// ---------------------------------------------------------------------------
// Prepack K,V into bf16x2 hi/lo fragment-order tiles (unchanged from R9).
// ---------------------------------------------------------------------------
__global__ __launch_bounds__(256)
void prepack_kv_kernel(const float* __restrict__ K, const float* __restrict__ V,
                       uint32_t* __restrict__ kpk, uint32_t* __restrict__ vpk)
{
    const int kti = blockIdx.x, kvh = blockIdx.y, b = blockIdx.z;
    const size_t tile = ((size_t)(b * KVHEADS + kvh) * 32 + kti) * 4096;
    uint32_t* kd = kpk + tile;
    uint32_t* vd = vpk + tile;
    const size_t kvStride = KVHEADS * HDIM;

    for (int w = threadIdx.x; w < 2048; w += 256) {
        int n  = w >> 5, j = w & 31;
        int kt = j >> 3, jj = j & 7;
        int t  = jj >> 1, hi = jj & 1;
        int d0 = kt * 16 + 2 * t + 8 * hi;

        const float* krow = K + (size_t)(b * SEQ + kti * 64 + n) * kvStride + kvh * HDIM;
        float k0 = krow[d0], k1 = krow[d0 + 1];
        uint32_t wh = bfpack(k0, k1);
        uint32_t wl = bfpack(k0 - bflo(wh), k1 - bfhi(wh));
        kd[w] = wh; kd[2048 + w] = wl;

        int key0 = kti * 64 + d0;
        const float* vb = V + (size_t)(b * SEQ + key0) * kvStride + kvh * HDIM + n;
        float v0 = vb[0], v1 = vb[kvStride];
        uint32_t uh = bfpack(v0, v1);
        uint32_t ul = bfpack(v0 - bflo(uh), v1 - bfhi(uh));
        vd[w] = uh; vd[2048 + w] = ul;
    }
}

// ---------------------------------------------------------------------------
// bf16 tensor-core causal flash attention (full 2-term; unchanged from R9).
// ---------------------------------------------------------------------------
#define AT_STRIDE 40
#define AT_SUB    2560
#define AT_BUF    10240
#define AT_SMEM   (2 * AT_BUF * 4)   // 81920 B

__global__ __launch_bounds__(128, 2)
void attn_bf16_kernel(const float* __restrict__ Q,
                      const uint32_t* __restrict__ kpk,
                      const uint32_t* __restrict__ vpk,
                      float* __restrict__ O)
{
    extern __shared__ uint32_t sm[];
    uint32_t smem_u32;
    {
        uint64_t a64;
        asm("cvta.to.shared.u64 %0, %1;" : "=l"(a64) : "l"(sm));
        smem_u32 = (uint32_t)a64;
    }

    const int qt  = (SEQ / 128 - 1) - blockIdx.x;
    const int h   = blockIdx.y;
    const int b   = blockIdx.z;
    const int kvh = h >> 2;
    const int tid  = threadIdx.x;
    const int lane = tid & 31;
    const int w    = tid >> 5;
    const int g    = lane >> 2;
    const int t    = lane & 3;

    uint32_t qh[2][4][4], ql[2][4][4];
    {
        const float* qb = Q + (size_t)(b * SEQ + qt * 128 + w * 32) * DMODEL + h * HDIM;
#pragma unroll
        for (int mt = 0; mt < 2; mt++) {
#pragma unroll
            for (int kt = 0; kt < 4; kt++) {
                int r0 = mt * 16 + g, r1 = r0 + 8;
                int c0 = kt * 16 + 2 * t, c2 = c0 + 8;
                float2 x0 = *(const float2*)(qb + (size_t)r0 * DMODEL + c0);
                float2 x1 = *(const float2*)(qb + (size_t)r1 * DMODEL + c0);
                float2 x2 = *(const float2*)(qb + (size_t)r0 * DMODEL + c2);
                float2 x3 = *(const float2*)(qb + (size_t)r1 * DMODEL + c2);
                x0.x *= 0.125f; x0.y *= 0.125f; x1.x *= 0.125f; x1.y *= 0.125f;
                x2.x *= 0.125f; x2.y *= 0.125f; x3.x *= 0.125f; x3.y *= 0.125f;
                uint32_t h0 = bfpack(x0.x, x0.y), h1 = bfpack(x1.x, x1.y);
                uint32_t h2 = bfpack(x2.x, x2.y), h3 = bfpack(x3.x, x3.y);
                qh[mt][kt][0] = h0; qh[mt][kt][1] = h1; qh[mt][kt][2] = h2; qh[mt][kt][3] = h3;
                ql[mt][kt][0] = bfpack(x0.x - bflo(h0), x0.y - bfhi(h0));
                ql[mt][kt][1] = bfpack(x1.x - bflo(h1), x1.y - bfhi(h1));
                ql[mt][kt][2] = bfpack(x2.x - bflo(h2), x2.y - bfhi(h2));
                ql[mt][kt][3] = bfpack(x3.x - bflo(h3), x3.y - bfhi(h3));
            }
        }
    }

    float o[2][8][4];
#pragma unroll
    for (int mt = 0; mt < 2; mt++)
#pragma unroll
        for (int nt = 0; nt < 8; nt++)
#pragma unroll
            for (int i = 0; i < 4; i++) o[mt][nt][i] = 0.f;
    float mrow[2][2] = { {-INFINITY, -INFINITY}, {-INFINITY, -INFINITY} };
    float lrow[2][2] = { {0.f, 0.f}, {0.f, 0.f} };

    const int last = 2 * qt + 1;
    const uint32_t* kbase_g = kpk + (size_t)(b * KVHEADS + kvh) * 32 * 4096;
    const uint32_t* vbase_g = vpk + (size_t)(b * KVHEADS + kvh) * 32 * 4096;

    auto stage = [&](int kti, int buf) {
        uint32_t dst = smem_u32 + buf * (AT_BUF * 4);
        const uint32_t* ks = kbase_g + (size_t)kti * 4096;
        const uint32_t* vs = vbase_g + (size_t)kti * 4096;
#pragma unroll
        for (int i = 0; i < 8; i++) {
            int c   = tid + i * 128;
            int sub = c >> 9;
            int r   = (c >> 3) & 63;
            int off = c & 7;
            uint32_t d = dst + (sub * AT_SUB + r * AT_STRIDE + off * 4) * 4;
            cpasync16(d, ks + (size_t)c * 4);
            cpasync16(d + 2 * AT_SUB * 4, vs + (size_t)c * 4);
        }
        asm volatile("cp.async.commit_group;" ::: "memory");
    };

    stage(0, 0);

    for (int kti = 0; kti <= last; kti++) {
        const int buf = kti & 1;
        if (kti < last) {
            __syncthreads();
            stage(kti + 1, buf ^ 1);
            asm volatile("cp.async.wait_group 1;" ::: "memory");
        } else {
            asm volatile("cp.async.wait_group 0;" ::: "memory");
        }
        __syncthreads();

        const uint32_t* sKh = sm + buf * AT_BUF;
        const uint32_t* sKl = sKh + AT_SUB;
        const uint32_t* sVh = sKh + 2 * AT_SUB;
        const uint32_t* sVl = sKh + 3 * AT_SUB;

        const int kb = kti * 64;
        bool act[2];
        act[0] = kb <= qt * 128 + w * 32 + 15;
        act[1] = kb <= qt * 128 + w * 32 + 31;
        if (!act[1]) continue;

        float s2[2][8][4];
#pragma unroll
        for (int mt = 0; mt < 2; mt++)
#pragma unroll
            for (int nt = 0; nt < 8; nt++)
#pragma unroll
                for (int i = 0; i < 4; i++) s2[mt][nt][i] = 0.f;

#pragma unroll
        for (int kt = 0; kt < 4; kt++) {
#pragma unroll
            for (int nt = 0; nt < 8; nt++) {
                uint2 bh = *(const uint2*)&sKh[(nt * 8 + g) * AT_STRIDE + kt * 8 + t * 2];
                uint2 bl = *(const uint2*)&sKl[(nt * 8 + g) * AT_STRIDE + kt * 8 + t * 2];
#pragma unroll
                for (int mt = 0; mt < 2; mt++) {
                    if (mt == 0 && !act[0]) continue;
                    mma16bf(s2[mt][nt], qh[mt][kt], bh.x, bh.y);
                    mma16bf(s2[mt][nt], ql[mt][kt], bh.x, bh.y);
                    mma16bf(s2[mt][nt], qh[mt][kt], bl.x, bl.y);
                }
            }
        }

        uint32_t ph2[2][8][2], pl2[2][8][2];
#pragma unroll
        for (int mt = 0; mt < 2; mt++) {
            if (mt == 0 && !act[0]) continue;
            int r0g = qt * 128 + w * 32 + mt * 16 + g;
            int r1g = r0g + 8;
            if (kb + 63 > r0g) {
#pragma unroll
                for (int nt = 0; nt < 8; nt++) {
                    int c0 = kb + nt * 8 + 2 * t, c1 = c0 + 1;
                    if (c0 > r0g) s2[mt][nt][0] = -INFINITY;
                    if (c1 > r0g) s2[mt][nt][1] = -INFINITY;
                    if (c0 > r1g) s2[mt][nt][2] = -INFINITY;
                    if (c1 > r1g) s2[mt][nt][3] = -INFINITY;
                }
            }
            float cm0 = -INFINITY, cm1 = -INFINITY;
#pragma unroll
            for (int nt = 0; nt < 8; nt++) {
                cm0 = fmaxf(cm0, fmaxf(s2[mt][nt][0], s2[mt][nt][1]));
                cm1 = fmaxf(cm1, fmaxf(s2[mt][nt][2], s2[mt][nt][3]));
            }
            cm0 = fmaxf(cm0, __shfl_xor_sync(0xffffffffu, cm0, 1));
            cm0 = fmaxf(cm0, __shfl_xor_sync(0xffffffffu, cm0, 2));
            cm1 = fmaxf(cm1, __shfl_xor_sync(0xffffffffu, cm1, 1));
            cm1 = fmaxf(cm1, __shfl_xor_sync(0xffffffffu, cm1, 2));
            float M0 = fmaxf(mrow[mt][0], cm0), M1 = fmaxf(mrow[mt][1], cm1);
            float sc0 = __expf(mrow[mt][0] - M0), sc1 = __expf(mrow[mt][1] - M1);
            float sum0 = 0.f, sum1 = 0.f;
#pragma unroll
            for (int nt = 0; nt < 8; nt++) {
                float p0 = __expf(s2[mt][nt][0] - M0);
                float p1 = __expf(s2[mt][nt][1] - M0);
                float p2 = __expf(s2[mt][nt][2] - M1);
                float p3 = __expf(s2[mt][nt][3] - M1);
                sum0 += p0 + p1; sum1 += p2 + p3;
                uint32_t w0 = bfpack(p0, p1), w1 = bfpack(p2, p3);
                ph2[mt][nt][0] = w0;
                ph2[mt][nt][1] = w1;
                pl2[mt][nt][0] = bfpack(p0 - bflo(w0), p1 - bfhi(w0));
                pl2[mt][nt][1] = bfpack(p2 - bflo(w1), p3 - bfhi(w1));
            }
            sum0 += __shfl_xor_sync(0xffffffffu, sum0, 1);
            sum0 += __shfl_xor_sync(0xffffffffu, sum0, 2);
            sum1 += __shfl_xor_sync(0xffffffffu, sum1, 1);
            sum1 += __shfl_xor_sync(0xffffffffu, sum1, 2);
            lrow[mt][0] = lrow[mt][0] * sc0 + sum0;
            lrow[mt][1] = lrow[mt][1] * sc1 + sum1;
#pragma unroll
            for (int nt = 0; nt < 8; nt++) {
                o[mt][nt][0] *= sc0; o[mt][nt][1] *= sc0;
                o[mt][nt][2] *= sc1; o[mt][nt][3] *= sc1;
            }
            mrow[mt][0] = M0; mrow[mt][1] = M1;
        }

#pragma unroll
        for (int kt = 0; kt < 4; kt++) {
#pragma unroll
            for (int nt = 0; nt < 8; nt++) {
                uint2 bh = *(const uint2*)&sVh[(nt * 8 + g) * AT_STRIDE + kt * 8 + t * 2];
                uint2 bl = *(const uint2*)&sVl[(nt * 8 + g) * AT_STRIDE + kt * 8 + t * 2];
#pragma unroll
                for (int mt = 0; mt < 2; mt++) {
                    if (mt == 0 && !act[0]) continue;
                    uint32_t ah[4] = { ph2[mt][2 * kt][0], ph2[mt][2 * kt][1],
                                       ph2[mt][2 * kt + 1][0], ph2[mt][2 * kt + 1][1] };
                    uint32_t al[4] = { pl2[mt][2 * kt][0], pl2[mt][2 * kt][1],
                                       pl2[mt][2 * kt + 1][0], pl2[mt][2 * kt + 1][1] };
                    mma16bf(o[mt][nt], ah, bh.x, bh.y);
                    mma16bf(o[mt][nt], ah, bl.x, bl.y);
                    mma16bf(o[mt][nt], al, bh.x, bh.y);
                }
            }
        }
    }

#pragma unroll
    for (int mt = 0; mt < 2; mt++) {
        float inv0 = 1.f / lrow[mt][0], inv1 = 1.f / lrow[mt][1];
        float* ob = O + (size_t)(b * SEQ + qt * 128 + w * 32 + mt * 16 + g) * DMODEL + h * HDIM;
#pragma unroll
        for (int nt = 0; nt < 8; nt++) {
            int co = nt * 8 + 2 * t;
            *(float2*)(ob + co)              = make_float2(o[mt][nt][0] * inv0, o[mt][nt][1] * inv0);
            *(float2*)(ob + 8 * DMODEL + co) = make_float2(o[mt][nt][2] * inv1, o[mt][nt][3] * inv1);
        }
    }
}

// ---------------------------------------------------------------------------
extern "C" void kernel_launch(void* const* d_in, const int* in_sizes, int n_in,
                              void* d_out, int out_size)
{
    const float* x  = (const float*)d_in[0];
    // d_in[1] = attention_mask: all-true by construction; not read.
    const float* wq = (const float*)d_in[2];
    const float* wk = (const float*)d_in[3];
    const float* wv = (const float*)d_in[4];
    const float* wo = (const float*)d_in[5];
    float* out = (float*)d_out;

    void *pq, *pk, *pv, *pao, *prt, *pkp, *pvp, *pxp, *paop, *pwp;
    cudaGetSymbolAddress(&pq,   g_q);
    cudaGetSymbolAddress(&pk,   g_k);
    cudaGetSymbolAddress(&pv,   g_v);
    cudaGetSymbolAddress(&pao,  g_ao);
    cudaGetSymbolAddress(&prt,  g_rope);
    cudaGetSymbolAddress(&pkp,  g_kpk);
    cudaGetSymbolAddress(&pvp,  g_vpk);
    cudaGetSymbolAddress(&pxp,  g_xpk);
    cudaGetSymbolAddress(&paop, g_aopk);
    cudaGetSymbolAddress(&pwp,  g_wpk);
    float*    qb   = (float*)pq;
    float*    kb   = (float*)pk;
    float*    vb   = (float*)pv;
    float*    aob  = (float*)pao;
    float2*   tbl  = (float2*)prt;
    uint32_t* kpk  = (uint32_t*)pkp;
    uint32_t* vpk  = (uint32_t*)pvp;
    uint32_t* xpk  = (uint32_t*)pxp;
    uint32_t* aopk = (uint32_t*)paop;
    uint32_t* wpk  = (uint32_t*)pwp;

    static int attr_set = 0;
    if (!attr_set) {
        cudaFuncSetAttribute(qkv_gemm2_kernel,
                             cudaFuncAttributeMaxDynamicSharedMemorySize, G2_SMEM);
        cudaFuncSetAttribute(o_gemm2_kernel,
                             cudaFuncAttributeMaxDynamicSharedMemorySize, G2_SMEM);
        cudaFuncSetAttribute(attn_bf16_kernel,
                             cudaFuncAttributeMaxDynamicSharedMemorySize, AT_SMEM);
        attr_set = 1;
    }

    // RoPE cos/sin table
    rope_table_kernel<<<(SEQ * 32 + 255) / 256, 256>>>(tbl);

    // Prepack operands to tf32 fragment order
    prepack_A_kernel<<<dim3(128, 32), 256>>>(x, xpk);
    prepack_B_kernel<<<dim3(128, 8), 256>>>(wq, wpk, 0);
    prepack_B_kernel<<<dim3(128, 2), 256>>>(wk, wpk, 8);
    prepack_B_kernel<<<dim3(128, 2), 256>>>(wv, wpk, 10);
    prepack_B_kernel<<<dim3(128, 8), 256>>>(wo, wpk, 12);

    // Fused QKV projection (RoPE fused into Q and K epilogues)
    qkv_gemm2_kernel<<<dim3(12, 32), 256, G2_SMEM>>>(xpk, wpk, qb, kb, vb, tbl);

    // Prepack K/V into bf16x2 fragment tiles
    prepack_kv_kernel<<<dim3(32, KVHEADS, BATCH), 256>>>(kb, vb, kpk, vpk);

    // Attention (bf16 tensor-core, 2-term everywhere)
    {
        dim3 grid(SEQ / 128, QHEADS, BATCH);
        attn_bf16_kernel<<<grid, 128, AT_SMEM>>>(qb, kpk, vpk, aob);
    }

    // Output projection
    prepack_A_kernel<<<dim3(128, 32), 256>>>(aob, aopk);
    o_gemm2_kernel<<<dim3(8, 32), 256, G2_SMEM>>>(aopk, wpk, out, tbl);
}

// round 17
// speedup vs baseline: 5.8023x; 1.0182x over previous
#include <cuda_runtime.h>
#include <math.h>
#include <stdint.h>

#define BATCH   2
#define SEQ     2048
#define DMODEL  2048
#define QHEADS  32
#define KVHEADS 8
#define HDIM    64
#define MROWS   (BATCH * SEQ)   // 4096

// ---------------- scratch (device globals; no runtime allocation) ----------
__device__ float    g_q  [MROWS * (QHEADS  * HDIM)];
__device__ float    g_k  [MROWS * (KVHEADS * HDIM)];
__device__ float    g_v  [MROWS * (KVHEADS * HDIM)];
__device__ float2   g_rope[SEQ * 32];
__device__ uint32_t g_kpk[BATCH * KVHEADS * 32 * 4096];
__device__ uint32_t g_vpk[BATCH * KVHEADS * 32 * 4096];
// tf32 fragment-packed GEMM operands
__device__ uint32_t g_xpk [32 * 128 * 2048];           // x   (A)
__device__ uint32_t g_aopk[32 * 128 * 2048];           // attention out (A), written packed
__device__ uint32_t g_wpk [20 * 128 * 4096];           // wq(0-7) wk(8-9) wv(10-11) wo(12-19)

// ---------------------------------------------------------------------------
__global__ void rope_table_kernel(float2* __restrict__ tbl)
{
    int i = blockIdx.x * blockDim.x + threadIdx.x;
    if (i >= SEQ * 32) return;
    int pair = i & 31;
    int pos  = i >> 5;
    double inv = pow(10000.0, -(2.0 * pair) / 64.0);
    double a   = (double)pos * inv;
    tbl[i] = make_float2((float)cos(a), (float)sin(a));
}

// ---------------------------------------------------------------------------
// helpers
// ---------------------------------------------------------------------------
__device__ __forceinline__ uint32_t f2tf(float f)
{
    uint32_t u;
    asm("cvt.rna.tf32.f32 %0, %1;" : "=r"(u) : "f"(f));
    return u;
}
__device__ __forceinline__ uint32_t bfpack(float lo, float hi)
{
    uint32_t d;
    asm("cvt.rn.bf16x2.f32 %0, %1, %2;" : "=r"(d) : "f"(hi), "f"(lo));
    return d;
}
__device__ __forceinline__ float bflo(uint32_t w) { return __uint_as_float(w << 16); }
__device__ __forceinline__ float bfhi(uint32_t w) { return __uint_as_float(w & 0xffff0000u); }

__device__ __forceinline__ void mma8(float* c, const uint32_t* a, const uint32_t* b)
{
    asm volatile(
        "mma.sync.aligned.m16n8k8.row.col.f32.tf32.tf32.f32 "
        "{%0,%1,%2,%3}, {%4,%5,%6,%7}, {%8,%9}, {%0,%1,%2,%3};"
        : "+f"(c[0]), "+f"(c[1]), "+f"(c[2]), "+f"(c[3])
        : "r"(a[0]), "r"(a[1]), "r"(a[2]), "r"(a[3]), "r"(b[0]), "r"(b[1]));
}
__device__ __forceinline__ void mma16bf(float* c, const uint32_t* a, uint32_t b0, uint32_t b1)
{
    asm volatile(
        "mma.sync.aligned.m16n8k16.row.col.f32.bf16.bf16.f32 "
        "{%0,%1,%2,%3}, {%4,%5,%6,%7}, {%8,%9}, {%0,%1,%2,%3};"
        : "+f"(c[0]), "+f"(c[1]), "+f"(c[2]), "+f"(c[3])
        : "r"(a[0]), "r"(a[1]), "r"(a[2]), "r"(a[3]), "r"(b0), "r"(b1));
}
__device__ __forceinline__ void cpasync16(uint32_t dst, const void* src)
{
    asm volatile("cp.async.cg.shared.global [%0], [%1], 16;" :: "r"(dst), "l"(src));
}

// ---------------------------------------------------------------------------
// Prepack A-operand (M x 2048 fp32) into tf32 fragment order:
// word((mtile,ktile),(mt,k8,lane,rg)) ; rg = k4*2 + hi ; lane = g*4 + t
// ---------------------------------------------------------------------------
__global__ __launch_bounds__(256)
void prepack_A_kernel(const float* __restrict__ src, uint32_t* __restrict__ dst)
{
    const int ktile = blockIdx.x, mtile = blockIdx.y;
    uint32_t* d = dst + ((size_t)mtile * 128 + ktile) * 2048;
    for (int w = threadIdx.x; w < 2048; w += 256) {
        int mt = w >> 8, k8 = (w >> 7) & 1, lane = (w >> 2) & 31, rg = w & 3;
        int g = lane >> 2, t = lane & 3, k4 = rg >> 1, hi = rg & 1;
        int m = mtile * 128 + mt * 16 + hi * 8 + g;
        int k = ktile * 16 + k8 * 8 + k4 * 4 + t;
        d[w] = f2tf(src[(size_t)m * 2048 + k]);
    }
}

// B-operand (N x 2048 fp32) into fragment order:
// word((ntile,ktile),(nt,k8,lane,b)) ; lane = g*4 + t (g = n&7) ; b = k4
// ---------------------------------------------------------------------------
__global__ __launch_bounds__(256)
void prepack_B_kernel(const float* __restrict__ src, uint32_t* __restrict__ dst, int base)
{
    const int ktile = blockIdx.x, n256 = blockIdx.y;
    uint32_t* d = dst + ((size_t)(base + n256) * 128 + ktile) * 4096;
    for (int w = threadIdx.x; w < 4096; w += 256) {
        int nt = w >> 7, k8 = (w >> 6) & 1, lane = (w >> 1) & 31, b = w & 1;
        int g = lane >> 2, t = lane & 3;
        int n = n256 * 256 + nt * 8 + g;
        int k = ktile * 16 + k8 * 8 + b * 4 + t;
        d[w] = f2tf(src[(size_t)n * 2048 + k]);
    }
}

// ---------------------------------------------------------------------------
// tf32 mma.sync GEMM on prepacked operands.
// CTA 128x128, 8 warps (wm 2 x wn 4), warp tile 64x32, K-slab 32,
// double-buffered cp.async; 2 blocks/SM.
// ---------------------------------------------------------------------------
#define G2_BUFW 8192                  // words/buffer: A 4096 + B 4096
#define G2_SMEM (2 * G2_BUFW * 4)     // 65536 B

__device__ __forceinline__ void gemm2_tile(
    const uint32_t* __restrict__ Apk, const uint32_t* __restrict__ Bptr,
    float* __restrict__ C, int ldc, int mtile, int col0, int rope,
    const float2* __restrict__ tbl)
{
    extern __shared__ uint32_t sm[];
    uint32_t smem_u32;
    { uint64_t a; asm("cvta.to.shared.u64 %0, %1;" : "=l"(a) : "l"(sm)); smem_u32 = (uint32_t)a; }

    const int tid = threadIdx.x, lane = tid & 31, w = tid >> 5;
    const int wm = w & 1, wn = w >> 1;
    const int g = lane >> 2, t = lane & 3;

    float acc[4][4][4];
#pragma unroll
    for (int mt = 0; mt < 4; mt++)
#pragma unroll
        for (int nt = 0; nt < 4; nt++)
#pragma unroll
            for (int i = 0; i < 4; i++) acc[mt][nt][i] = 0.f;

    const uint32_t* Aslab = Apk + (size_t)mtile * 128 * 2048;

    auto stage = [&](int s, int buf) {
        uint32_t dst = smem_u32 + (uint32_t)buf * (G2_BUFW * 4);
        const uint32_t* as = Aslab + (size_t)(s * 2) * 2048;   // 4096 w contiguous
#pragma unroll
        for (int i = 0; i < 4; i++) {
            int c = tid + i * 256;
            cpasync16(dst + c * 16, as + (size_t)c * 4);
        }
#pragma unroll
        for (int ktl = 0; ktl < 2; ktl++) {
            const uint32_t* bs = Bptr + (size_t)(s * 2 + ktl) * 4096;  // 2048 w each
#pragma unroll
            for (int i = 0; i < 2; i++) {
                int c = tid + i * 256;
                cpasync16(dst + (4096 + ktl * 2048 + c * 4) * 4, bs + (size_t)c * 4);
            }
        }
        asm volatile("cp.async.commit_group;" ::: "memory");
    };

    stage(0, 0);

    for (int s = 0; s < 64; s++) {
        const int buf = s & 1;
        if (s < 63) {
            __syncthreads();
            stage(s + 1, buf ^ 1);
            asm volatile("cp.async.wait_group 1;" ::: "memory");
        } else {
            asm volatile("cp.async.wait_group 0;" ::: "memory");
        }
        __syncthreads();

        const uint32_t* bA = sm + buf * G2_BUFW;
        const uint32_t* bB = bA + 4096;
#pragma unroll
        for (int ktl = 0; ktl < 2; ktl++) {
#pragma unroll
            for (int k8 = 0; k8 < 2; k8++) {
                uint4 af[4];
                uint2 bf[4];
#pragma unroll
                for (int mt = 0; mt < 4; mt++)
                    af[mt] = *(const uint4*)&bA[ktl * 2048 + (wm * 4 + mt) * 256 + k8 * 128 + lane * 4];
#pragma unroll
                for (int nt = 0; nt < 4; nt++)
                    bf[nt] = *(const uint2*)&bB[ktl * 2048 + (wn * 4 + nt) * 128 + k8 * 64 + lane * 2];
#pragma unroll
                for (int mt = 0; mt < 4; mt++)
#pragma unroll
                    for (int nt = 0; nt < 4; nt++)
                        mma8(acc[mt][nt], (const uint32_t*)&af[mt], (const uint32_t*)&bf[nt]);
            }
        }
    }

    // ---- epilogue (+ optional fused RoPE on interleaved pairs) ----
    const int row0 = mtile * 128 + wm * 64;
#pragma unroll
    for (int mt = 0; mt < 4; mt++) {
        int r0 = row0 + mt * 16 + g;
#pragma unroll
        for (int nt = 0; nt < 4; nt++) {
            int c = col0 + wn * 32 + nt * 8 + 2 * t;
            float v0 = acc[mt][nt][0], v1 = acc[mt][nt][1];
            float v2 = acc[mt][nt][2], v3 = acc[mt][nt][3];
            if (rope) {
                int pair = (c & 63) >> 1;
                float2 cs1 = tbl[(r0       & (SEQ - 1)) * 32 + pair];
                float2 cs2 = tbl[((r0 + 8) & (SEQ - 1)) * 32 + pair];
                float o0 = v0 * cs1.x - v1 * cs1.y;
                float o1 = v1 * cs1.x + v0 * cs1.y;
                float o2 = v2 * cs2.x - v3 * cs2.y;
                float o3 = v3 * cs2.x + v2 * cs2.y;
                v0 = o0; v1 = o1; v2 = o2; v3 = o3;
            }
            *(float2*)&C[(size_t)r0 * ldc + c]       = make_float2(v0, v1);
            *(float2*)&C[(size_t)(r0 + 8) * ldc + c] = make_float2(v2, v3);
        }
    }
}

__global__ __launch_bounds__(256, 2)
void qkv_gemm2_kernel(const uint32_t* __restrict__ xpk,
                      const uint32_t* __restrict__ wpk,
                      float* __restrict__ qb, float* __restrict__ kb,
                      float* __restrict__ vb, const float2* __restrict__ tbl)
{
    const int bx = blockIdx.x;
    float* C; int ldc, col0, rope, widx, half;
    if (bx < 16)      { C = qb; ldc = 2048; col0 = bx * 128;
                        rope = 1; widx = bx >> 1;              half = bx & 1; }
    else if (bx < 20) { int l = bx - 16; C = kb; ldc = 512; col0 = l * 128;
                        rope = 1; widx = 8 + (l >> 1);         half = l & 1; }
    else              { int l = bx - 20; C = vb; ldc = 512; col0 = l * 128;
                        rope = 0; widx = 10 + (l >> 1);        half = l & 1; }
    const uint32_t* Bptr = wpk + (size_t)widx * 128 * 4096 + half * 2048;
    gemm2_tile(xpk, Bptr, C, ldc, blockIdx.y, col0, rope, tbl);
}

__global__ __launch_bounds__(256, 2)
void o_gemm2_kernel(const uint32_t* __restrict__ aopk,
                    const uint32_t* __restrict__ wpk,
                    float* __restrict__ out, const float2* __restrict__ tbl)
{
    const int bx = blockIdx.x;
    const uint32_t* Bptr = wpk + (size_t)(12 + (bx >> 1)) * 128 * 4096 + (bx & 1) * 2048;
    gemm2_tile(aopk, Bptr, out, 2048, blockIdx.y, bx * 128, 0, tbl);
}

// ---------------------------------------------------------------------------
// Prepack K,V into bf16x2 hi/lo fragment-order tiles (unchanged).
// ---------------------------------------------------------------------------
__global__ __launch_bounds__(256)
void prepack_kv_kernel(const float* __restrict__ K, const float* __restrict__ V,
                       uint32_t* __restrict__ kpk, uint32_t* __restrict__ vpk)
{
    const int kti = blockIdx.x, kvh = blockIdx.y, b = blockIdx.z;
    const size_t tile = ((size_t)(b * KVHEADS + kvh) * 32 + kti) * 4096;
    uint32_t* kd = kpk + tile;
    uint32_t* vd = vpk + tile;
    const size_t kvStride = KVHEADS * HDIM;

    for (int w = threadIdx.x; w < 2048; w += 256) {
        int n  = w >> 5, j = w & 31;
        int kt = j >> 3, jj = j & 7;
        int t  = jj >> 1, hi = jj & 1;
        int d0 = kt * 16 + 2 * t + 8 * hi;

        const float* krow = K + (size_t)(b * SEQ + kti * 64 + n) * kvStride + kvh * HDIM;
        float k0 = krow[d0], k1 = krow[d0 + 1];
        uint32_t wh = bfpack(k0, k1);
        uint32_t wl = bfpack(k0 - bflo(wh), k1 - bfhi(wh));
        kd[w] = wh; kd[2048 + w] = wl;

        int key0 = kti * 64 + d0;
        const float* vb = V + (size_t)(b * SEQ + key0) * kvStride + kvh * HDIM + n;
        float v0 = vb[0], v1 = vb[kvStride];
        uint32_t uh = bfpack(v0, v1);
        uint32_t ul = bfpack(v0 - bflo(uh), v1 - bfhi(uh));
        vd[w] = uh; vd[2048 + w] = ul;
    }
}

// ---------------------------------------------------------------------------
// bf16 tensor-core causal flash attention (full 2-term). Output written
// DIRECTLY in packed tf32 A-fragment order (feeds o_gemm2 without prepack).
// ---------------------------------------------------------------------------
#define AT_STRIDE 40
#define AT_SUB    2560
#define AT_BUF    10240
#define AT_SMEM   (2 * AT_BUF * 4)   // 81920 B

__global__ __launch_bounds__(128, 2)
void attn_bf16_kernel(const float* __restrict__ Q,
                      const uint32_t* __restrict__ kpk,
                      const uint32_t* __restrict__ vpk,
                      uint32_t* __restrict__ AOpk)
{
    extern __shared__ uint32_t sm[];
    uint32_t smem_u32;
    {
        uint64_t a64;
        asm("cvta.to.shared.u64 %0, %1;" : "=l"(a64) : "l"(sm));
        smem_u32 = (uint32_t)a64;
    }

    const int qt  = (SEQ / 128 - 1) - blockIdx.x;
    const int h   = blockIdx.y;
    const int b   = blockIdx.z;
    const int kvh = h >> 2;
    const int tid  = threadIdx.x;
    const int lane = tid & 31;
    const int w    = tid >> 5;
    const int g    = lane >> 2;
    const int t    = lane & 3;

    uint32_t qh[2][4][4], ql[2][4][4];
    {
        const float* qb = Q + (size_t)(b * SEQ + qt * 128 + w * 32) * DMODEL + h * HDIM;
#pragma unroll
        for (int mt = 0; mt < 2; mt++) {
#pragma unroll
            for (int kt = 0; kt < 4; kt++) {
                int r0 = mt * 16 + g, r1 = r0 + 8;
                int c0 = kt * 16 + 2 * t, c2 = c0 + 8;
                float2 x0 = *(const float2*)(qb + (size_t)r0 * DMODEL + c0);
                float2 x1 = *(const float2*)(qb + (size_t)r1 * DMODEL + c0);
                float2 x2 = *(const float2*)(qb + (size_t)r0 * DMODEL + c2);
                float2 x3 = *(const float2*)(qb + (size_t)r1 * DMODEL + c2);
                x0.x *= 0.125f; x0.y *= 0.125f; x1.x *= 0.125f; x1.y *= 0.125f;
                x2.x *= 0.125f; x2.y *= 0.125f; x3.x *= 0.125f; x3.y *= 0.125f;
                uint32_t h0 = bfpack(x0.x, x0.y), h1 = bfpack(x1.x, x1.y);
                uint32_t h2 = bfpack(x2.x, x2.y), h3 = bfpack(x3.x, x3.y);
                qh[mt][kt][0] = h0; qh[mt][kt][1] = h1; qh[mt][kt][2] = h2; qh[mt][kt][3] = h3;
                ql[mt][kt][0] = bfpack(x0.x - bflo(h0), x0.y - bfhi(h0));
                ql[mt][kt][1] = bfpack(x1.x - bflo(h1), x1.y - bfhi(h1));
                ql[mt][kt][2] = bfpack(x2.x - bflo(h2), x2.y - bfhi(h2));
                ql[mt][kt][3] = bfpack(x3.x - bflo(h3), x3.y - bfhi(h3));
            }
        }
    }

    float o[2][8][4];
#pragma unroll
    for (int mt = 0; mt < 2; mt++)
#pragma unroll
        for (int nt = 0; nt < 8; nt++)
#pragma unroll
            for (int i = 0; i < 4; i++) o[mt][nt][i] = 0.f;
    float mrow[2][2] = { {-INFINITY, -INFINITY}, {-INFINITY, -INFINITY} };
    float lrow[2][2] = { {0.f, 0.f}, {0.f, 0.f} };

    const int last = 2 * qt + 1;
    const uint32_t* kbase_g = kpk + (size_t)(b * KVHEADS + kvh) * 32 * 4096;
    const uint32_t* vbase_g = vpk + (size_t)(b * KVHEADS + kvh) * 32 * 4096;

    auto stage = [&](int kti, int buf) {
        uint32_t dst = smem_u32 + buf * (AT_BUF * 4);
        const uint32_t* ks = kbase_g + (size_t)kti * 4096;
        const uint32_t* vs = vbase_g + (size_t)kti * 4096;
#pragma unroll
        for (int i = 0; i < 8; i++) {
            int c   = tid + i * 128;
            int sub = c >> 9;
            int r   = (c >> 3) & 63;
            int off = c & 7;
            uint32_t d = dst + (sub * AT_SUB + r * AT_STRIDE + off * 4) * 4;
            cpasync16(d, ks + (size_t)c * 4);
            cpasync16(d + 2 * AT_SUB * 4, vs + (size_t)c * 4);
        }
        asm volatile("cp.async.commit_group;" ::: "memory");
    };

    stage(0, 0);

    for (int kti = 0; kti <= last; kti++) {
        const int buf = kti & 1;
        if (kti < last) {
            __syncthreads();
            stage(kti + 1, buf ^ 1);
            asm volatile("cp.async.wait_group 1;" ::: "memory");
        } else {
            asm volatile("cp.async.wait_group 0;" ::: "memory");
        }
        __syncthreads();

        const uint32_t* sKh = sm + buf * AT_BUF;
        const uint32_t* sKl = sKh + AT_SUB;
        const uint32_t* sVh = sKh + 2 * AT_SUB;
        const uint32_t* sVl = sKh + 3 * AT_SUB;

        const int kb = kti * 64;
        bool act[2];
        act[0] = kb <= qt * 128 + w * 32 + 15;
        act[1] = kb <= qt * 128 + w * 32 + 31;
        if (!act[1]) continue;

        float s2[2][8][4];
#pragma unroll
        for (int mt = 0; mt < 2; mt++)
#pragma unroll
            for (int nt = 0; nt < 8; nt++)
#pragma unroll
                for (int i = 0; i < 4; i++) s2[mt][nt][i] = 0.f;

#pragma unroll
        for (int kt = 0; kt < 4; kt++) {
#pragma unroll
            for (int nt = 0; nt < 8; nt++) {
                uint2 bh = *(const uint2*)&sKh[(nt * 8 + g) * AT_STRIDE + kt * 8 + t * 2];
                uint2 bl = *(const uint2*)&sKl[(nt * 8 + g) * AT_STRIDE + kt * 8 + t * 2];
#pragma unroll
                for (int mt = 0; mt < 2; mt++) {
                    if (mt == 0 && !act[0]) continue;
                    mma16bf(s2[mt][nt], qh[mt][kt], bh.x, bh.y);
                    mma16bf(s2[mt][nt], ql[mt][kt], bh.x, bh.y);
                    mma16bf(s2[mt][nt], qh[mt][kt], bl.x, bl.y);
                }
            }
        }

        uint32_t ph2[2][8][2], pl2[2][8][2];
#pragma unroll
        for (int mt = 0; mt < 2; mt++) {
            if (mt == 0 && !act[0]) continue;
            int r0g = qt * 128 + w * 32 + mt * 16 + g;
            int r1g = r0g + 8;
            if (kb + 63 > r0g) {
#pragma unroll
                for (int nt = 0; nt < 8; nt++) {
                    int c0 = kb + nt * 8 + 2 * t, c1 = c0 + 1;
                    if (c0 > r0g) s2[mt][nt][0] = -INFINITY;
                    if (c1 > r0g) s2[mt][nt][1] = -INFINITY;
                    if (c0 > r1g) s2[mt][nt][2] = -INFINITY;
                    if (c1 > r1g) s2[mt][nt][3] = -INFINITY;
                }
            }
            float cm0 = -INFINITY, cm1 = -INFINITY;
#pragma unroll
            for (int nt = 0; nt < 8; nt++) {
                cm0 = fmaxf(cm0, fmaxf(s2[mt][nt][0], s2[mt][nt][1]));
                cm1 = fmaxf(cm1, fmaxf(s2[mt][nt][2], s2[mt][nt][3]));
            }
            cm0 = fmaxf(cm0, __shfl_xor_sync(0xffffffffu, cm0, 1));
            cm0 = fmaxf(cm0, __shfl_xor_sync(0xffffffffu, cm0, 2));
            cm1 = fmaxf(cm1, __shfl_xor_sync(0xffffffffu, cm1, 1));
            cm1 = fmaxf(cm1, __shfl_xor_sync(0xffffffffu, cm1, 2));
            float M0 = fmaxf(mrow[mt][0], cm0), M1 = fmaxf(mrow[mt][1], cm1);
            float sc0 = __expf(mrow[mt][0] - M0), sc1 = __expf(mrow[mt][1] - M1);
            float sum0 = 0.f, sum1 = 0.f;
#pragma unroll
            for (int nt = 0; nt < 8; nt++) {
                float p0 = __expf(s2[mt][nt][0] - M0);
                float p1 = __expf(s2[mt][nt][1] - M0);
                float p2 = __expf(s2[mt][nt][2] - M1);
                float p3 = __expf(s2[mt][nt][3] - M1);
                sum0 += p0 + p1; sum1 += p2 + p3;
                uint32_t w0 = bfpack(p0, p1), w1 = bfpack(p2, p3);
                ph2[mt][nt][0] = w0;
                ph2[mt][nt][1] = w1;
                pl2[mt][nt][0] = bfpack(p0 - bflo(w0), p1 - bfhi(w0));
                pl2[mt][nt][1] = bfpack(p2 - bflo(w1), p3 - bfhi(w1));
            }
            sum0 += __shfl_xor_sync(0xffffffffu, sum0, 1);
            sum0 += __shfl_xor_sync(0xffffffffu, sum0, 2);
            sum1 += __shfl_xor_sync(0xffffffffu, sum1, 1);
            sum1 += __shfl_xor_sync(0xffffffffu, sum1, 2);
            lrow[mt][0] = lrow[mt][0] * sc0 + sum0;
            lrow[mt][1] = lrow[mt][1] * sc1 + sum1;
#pragma unroll
            for (int nt = 0; nt < 8; nt++) {
                o[mt][nt][0] *= sc0; o[mt][nt][1] *= sc0;
                o[mt][nt][2] *= sc1; o[mt][nt][3] *= sc1;
            }
            mrow[mt][0] = M0; mrow[mt][1] = M1;
        }

#pragma unroll
        for (int kt = 0; kt < 4; kt++) {
#pragma unroll
            for (int nt = 0; nt < 8; nt++) {
                uint2 bh = *(const uint2*)&sVh[(nt * 8 + g) * AT_STRIDE + kt * 8 + t * 2];
                uint2 bl = *(const uint2*)&sVl[(nt * 8 + g) * AT_STRIDE + kt * 8 + t * 2];
#pragma unroll
                for (int mt = 0; mt < 2; mt++) {
                    if (mt == 0 && !act[0]) continue;
                    uint32_t ah[4] = { ph2[mt][2 * kt][0], ph2[mt][2 * kt][1],
                                       ph2[mt][2 * kt + 1][0], ph2[mt][2 * kt + 1][1] };
                    uint32_t al[4] = { pl2[mt][2 * kt][0], pl2[mt][2 * kt][1],
                                       pl2[mt][2 * kt + 1][0], pl2[mt][2 * kt + 1][1] };
                    mma16bf(o[mt][nt], ah, bh.x, bh.y);
                    mma16bf(o[mt][nt], ah, bl.x, bl.y);
                    mma16bf(o[mt][nt], al, bh.x, bh.y);
                }
            }
        }
    }

    // ---- finalize: write packed tf32 A-fragment words directly ----
    const int mbase = b * SEQ + qt * 128 + w * 32;
#pragma unroll
    for (int mt2 = 0; mt2 < 2; mt2++) {
        float inv0 = 1.f / lrow[mt2][0], inv1 = 1.f / lrow[mt2][1];
#pragma unroll
        for (int nt = 0; nt < 8; nt++) {
#pragma unroll
            for (int i = 0; i < 4; i++) {
                int hi = i >> 1, dl = i & 1;
                float val = o[mt2][nt][i] * (hi ? inv1 : inv0);
                int m = mbase + mt2 * 16 + hi * 8 + g;
                int k = h * HDIM + nt * 8 + 2 * t + dl;
                int mtile = m >> 7, mt = (m >> 4) & 7;
                int ktile = k >> 4, k8 = (k >> 3) & 1, k4 = (k >> 2) & 1, tp = k & 3;
                size_t addr = ((size_t)(mtile * 128 + ktile)) * 2048
                            + mt * 256 + k8 * 128 + (g * 4 + tp) * 4 + (k4 * 2 + hi);
                AOpk[addr] = f2tf(val);
            }
        }
    }
}

// ---------------------------------------------------------------------------
extern "C" void kernel_launch(void* const* d_in, const int* in_sizes, int n_in,
                              void* d_out, int out_size)
{
    const float* x  = (const float*)d_in[0];
    // d_in[1] = attention_mask: all-true by construction; not read.
    const float* wq = (const float*)d_in[2];
    const float* wk = (const float*)d_in[3];
    const float* wv = (const float*)d_in[4];
    const float* wo = (const float*)d_in[5];
    float* out = (float*)d_out;

    void *pq, *pk, *pv, *prt, *pkp, *pvp, *pxp, *paop, *pwp;
    cudaGetSymbolAddress(&pq,   g_q);
    cudaGetSymbolAddress(&pk,   g_k);
    cudaGetSymbolAddress(&pv,   g_v);
    cudaGetSymbolAddress(&prt,  g_rope);
    cudaGetSymbolAddress(&pkp,  g_kpk);
    cudaGetSymbolAddress(&pvp,  g_vpk);
    cudaGetSymbolAddress(&pxp,  g_xpk);
    cudaGetSymbolAddress(&paop, g_aopk);
    cudaGetSymbolAddress(&pwp,  g_wpk);
    float*    qb   = (float*)pq;
    float*    kb   = (float*)pk;
    float*    vb   = (float*)pv;
    float2*   tbl  = (float2*)prt;
    uint32_t* kpk  = (uint32_t*)pkp;
    uint32_t* vpk  = (uint32_t*)pvp;
    uint32_t* xpk  = (uint32_t*)pxp;
    uint32_t* aopk = (uint32_t*)paop;
    uint32_t* wpk  = (uint32_t*)pwp;

    static int attr_set = 0;
    if (!attr_set) {
        cudaFuncSetAttribute(qkv_gemm2_kernel,
                             cudaFuncAttributeMaxDynamicSharedMemorySize, G2_SMEM);
        cudaFuncSetAttribute(o_gemm2_kernel,
                             cudaFuncAttributeMaxDynamicSharedMemorySize, G2_SMEM);
        cudaFuncSetAttribute(attn_bf16_kernel,
                             cudaFuncAttributeMaxDynamicSharedMemorySize, AT_SMEM);
        attr_set = 1;
    }

    // RoPE cos/sin table
    rope_table_kernel<<<(SEQ * 32 + 255) / 256, 256>>>(tbl);

    // Prepack operands to tf32 fragment order
    prepack_A_kernel<<<dim3(128, 32), 256>>>(x, xpk);
    prepack_B_kernel<<<dim3(128, 8), 256>>>(wq, wpk, 0);
    prepack_B_kernel<<<dim3(128, 2), 256>>>(wk, wpk, 8);
    prepack_B_kernel<<<dim3(128, 2), 256>>>(wv, wpk, 10);
    prepack_B_kernel<<<dim3(128, 8), 256>>>(wo, wpk, 12);

    // Fused QKV projection (RoPE fused into Q and K epilogues)
    qkv_gemm2_kernel<<<dim3(24, 32), 256, G2_SMEM>>>(xpk, wpk, qb, kb, vb, tbl);

    // Prepack K/V into bf16x2 fragment tiles
    prepack_kv_kernel<<<dim3(32, KVHEADS, BATCH), 256>>>(kb, vb, kpk, vpk);

    // Attention (writes packed-A fragments for the output projection directly)
    {
        dim3 grid(SEQ / 128, QHEADS, BATCH);
        attn_bf16_kernel<<<grid, 128, AT_SMEM>>>(qb, kpk, vpk, aopk);
    }

    // Output projection
    o_gemm2_kernel<<<dim3(16, 32), 256, G2_SMEM>>>(aopk, wpk, out, tbl);
}